// round 9
// baseline (speedup 1.0000x reference)
#include <cuda_runtime.h>
#include <cuda_bf16.h>
#include <math.h>
#include <stdint.h>

#define B_  2
#define T_  1024
#define C_  2048
#define NH  16
#define KH  4
#define H_  128
#define M_  (B_*T_)
#define KV  (KH*H_)     // 512

// fp32 scratch
__device__ float g_q[M_ * C_];
__device__ float g_k[M_ * KV];
__device__ float g_enc[M_ * C_];
// int8 quantized operands (digit1, digit2) + per-row scales
__device__ int8_t g_xq1[M_*C_],  g_xq2[M_*C_];
__device__ float  g_sx[M_];
__device__ int8_t g_wqq1[C_*C_], g_wqq2[C_*C_];   // [N,K]
__device__ float  g_swq[C_];
__device__ int8_t g_wkq1[KV*C_], g_wkq2[KV*C_];
__device__ float  g_swk[KV];
__device__ int8_t g_wvq1[KV*C_], g_wvq2[KV*C_];
__device__ float  g_swv[KV];
__device__ int8_t g_woq1[C_*C_], g_woq2[C_*C_];
__device__ float  g_swo[C_];
__device__ int8_t g_eq1[M_*C_],  g_eq2[M_*C_];
__device__ float  g_se[M_];
// bf16 split operands for attention
__device__ __nv_bfloat16 g_qh[M_*C_],  g_ql[M_*C_];
__device__ __nv_bfloat16 g_kh[M_*KV],  g_kl[M_*KV];
__device__ __nv_bfloat16 g_vh[M_*KV],  g_vl[M_*KV];

// ---------------- helpers ----------------
__device__ __forceinline__ void ldsm_x4(uint32_t& r0, uint32_t& r1, uint32_t& r2,
                                        uint32_t& r3, uint32_t addr) {
    asm volatile("ldmatrix.sync.aligned.m8n8.x4.shared.b16 {%0,%1,%2,%3}, [%4];"
                 : "=r"(r0), "=r"(r1), "=r"(r2), "=r"(r3) : "r"(addr));
}
__device__ __forceinline__ void ldsm_x2(uint32_t& r0, uint32_t& r1, uint32_t addr) {
    asm volatile("ldmatrix.sync.aligned.m8n8.x2.shared.b16 {%0,%1}, [%2];"
                 : "=r"(r0), "=r"(r1) : "r"(addr));
}
__device__ __forceinline__ void ldsm_x2t(uint32_t& r0, uint32_t& r1, uint32_t addr) {
    asm volatile("ldmatrix.sync.aligned.m8n8.x2.trans.shared.b16 {%0,%1}, [%2];"
                 : "=r"(r0), "=r"(r1) : "r"(addr));
}
__device__ __forceinline__ void mma16816(float* c, const uint32_t* a, const uint32_t* b) {
    asm volatile("mma.sync.aligned.m16n8k16.row.col.f32.bf16.bf16.f32 "
                 "{%0,%1,%2,%3}, {%4,%5,%6,%7}, {%8,%9}, {%0,%1,%2,%3};"
                 : "+f"(c[0]), "+f"(c[1]), "+f"(c[2]), "+f"(c[3])
                 : "r"(a[0]), "r"(a[1]), "r"(a[2]), "r"(a[3]), "r"(b[0]), "r"(b[1]));
}
__device__ __forceinline__ void imma16832(int32_t* c, const uint32_t* a, const uint32_t* b) {
    asm volatile("mma.sync.aligned.m16n8k32.row.col.s32.s8.s8.s32 "
                 "{%0,%1,%2,%3}, {%4,%5,%6,%7}, {%8,%9}, {%0,%1,%2,%3};"
                 : "+r"(c[0]), "+r"(c[1]), "+r"(c[2]), "+r"(c[3])
                 : "r"(a[0]), "r"(a[1]), "r"(a[2]), "r"(a[3]), "r"(b[0]), "r"(b[1]));
}
__device__ __forceinline__ uint32_t pack_bf2(__nv_bfloat16 a, __nv_bfloat16 b) {
    __nv_bfloat162 t = __halves2bfloat162(a, b);
    return *reinterpret_cast<uint32_t*>(&t);
}
__device__ __forceinline__ uint32_t pack_hi2(float x, float y) {
    return pack_bf2(__float2bfloat16(x), __float2bfloat16(y));
}
__device__ __forceinline__ uint32_t pack_lo2(float x, float y) {
    __nv_bfloat16 hx = __float2bfloat16(x), hy = __float2bfloat16(y);
    return pack_bf2(__float2bfloat16(x - __bfloat162float(hx)),
                    __float2bfloat16(y - __bfloat162float(hy)));
}
__device__ __forceinline__ void cp16(uint32_t s, const void* g) {
    asm volatile("cp.async.cg.shared.global [%0], [%1], 16;" :: "r"(s), "l"(g));
}
__device__ __forceinline__ void cp_commit() { asm volatile("cp.async.commit_group;"); }
template<int N> __device__ __forceinline__ void cp_wait() {
    asm volatile("cp.async.wait_group %0;" :: "n"(N));
}
__device__ __forceinline__ uint32_t smem_u32(const void* p) {
    return (uint32_t)__cvta_generic_to_shared(p);
}

// ---------------------------------------------------------------------------
// Row quantization: per row of [rows, D]: s = max|x|/127; a1=rint(x/s),
// a2=rint((x/s-a1)*254). One block per row.
// ---------------------------------------------------------------------------
__global__ void quant_rows(const float* __restrict__ in, int8_t* __restrict__ q1,
                           int8_t* __restrict__ q2, float* __restrict__ sc, int D) {
    __shared__ float sx[2048];
    __shared__ float swr[8];
    const int row = blockIdx.x;
    const int tid = threadIdx.x;
    const int lane = tid & 31, warp = tid >> 5;
    const float* rp = in + (size_t)row * D;

    float m = 0.f;
    for (int d = tid; d < D; d += 256) {
        float v = rp[d];
        sx[d] = v;
        m = fmaxf(m, fabsf(v));
    }
    #pragma unroll
    for (int off = 16; off > 0; off >>= 1)
        m = fmaxf(m, __shfl_xor_sync(0xffffffffu, m, off));
    if (lane == 0) swr[warp] = m;
    __syncthreads();
    float tot = 0.f;
    #pragma unroll
    for (int w = 0; w < 8; w++) tot = fmaxf(tot, swr[w]);
    const float s = fmaxf(tot, 1e-20f) * (1.0f / 127.0f);
    const float inv = 1.0f / s;
    if (tid == 0) sc[row] = s;

    for (int d = tid; d < D; d += 256) {
        float v = sx[d] * inv;
        float a1 = rintf(v);
        float a2 = rintf((v - a1) * 254.0f);
        q1[(size_t)row * D + d] = (int8_t)(int)a1;
        q2[(size_t)row * D + d] = (int8_t)(int)a2;
    }
}

// Column max of W[K,N] -> sB[n] = max/127
__global__ void colmax(const float* __restrict__ W, float* __restrict__ sB, int K, int N) {
    int n = blockIdx.x * 256 + threadIdx.x;
    if (n < N) {
        float m = 0.f;
        for (int k = 0; k < K; k++) m = fmaxf(m, fabsf(W[(size_t)k * N + n]));
        sB[n] = fmaxf(m, 1e-20f) * (1.0f / 127.0f);
    }
}

// Transpose + quantize: W[K,N] fp32 -> q1/q2[N,K] s8 using sB[n]
__global__ void tquant(const float* __restrict__ W, const float* __restrict__ sB,
                       int8_t* __restrict__ q1, int8_t* __restrict__ q2, int K, int N) {
    __shared__ float t[32][33];
    const int n0 = blockIdx.x * 32, k0 = blockIdx.y * 32;
    const int tx = threadIdx.x, ty = threadIdx.y;
    #pragma unroll
    for (int i = 0; i < 4; i++)
        t[ty + i * 8][tx] = W[(size_t)(k0 + ty + i * 8) * N + n0 + tx];
    __syncthreads();
    #pragma unroll
    for (int i = 0; i < 4; i++) {
        int n = n0 + ty + i * 8;
        float inv = 1.0f / sB[n];
        float v = t[tx][ty + i * 8] * inv;
        float a1 = rintf(v);
        float a2 = rintf((v - a1) * 254.0f);
        size_t o = (size_t)n * K + k0 + tx;
        q1[o] = (int8_t)(int)a1;
        q2[o] = (int8_t)(int)a2;
    }
}

// ---------------------------------------------------------------------------
// INT8 two-digit GEMM: C[M,N] = (sA*sB) * (S11 + S12/254), tile 128x128,
// BK=64, 512 threads (4x4 warps, warp tile 32x32), 2-stage cp.async.
// ---------------------------------------------------------------------------
#define IBK  64
#define IST  80                 // bytes per smem row slot (conflict-free)
#define ITILE (128*IST)         // 10240 B
#define ISTG (4*ITILE)          // A1,A2,B1,B2 per stage
#define IG_SMEM (2*ISTG)        // 81920 B

template<int OUTMODE>   // 0: fp32, 1: split bf16
__device__ __forceinline__ void igemm_body(
    const int8_t* __restrict__ A1, const int8_t* __restrict__ A2, const float* __restrict__ sA,
    const int8_t* __restrict__ B1, const int8_t* __restrict__ B2, const float* __restrict__ sB,
    float* __restrict__ Cf, __nv_bfloat16* __restrict__ Ch, __nv_bfloat16* __restrict__ Cl,
    int N, int K, int bm0, int bn0)
{
    extern __shared__ int8_t ism[];
    const uint32_t smB = smem_u32(ism);
    const int tid = threadIdx.x;
    const int lane = tid & 31;
    const int warp = tid >> 5;
    const int wm = (warp >> 2) * 32;
    const int wn = (warp & 3) * 32;

    const int pr = tid >> 2, pc = (tid & 3) * 16;

    auto issue = [&](int st, int k0) {
        uint32_t s0 = smB + (uint32_t)st * ISTG + (uint32_t)pr * IST + pc;
        cp16(s0,             A1 + (size_t)(bm0 + pr) * K + k0 + pc);
        cp16(s0 + ITILE,     A2 + (size_t)(bm0 + pr) * K + k0 + pc);
        cp16(s0 + 2 * ITILE, B1 + (size_t)(bn0 + pr) * K + k0 + pc);
        cp16(s0 + 3 * ITILE, B2 + (size_t)(bn0 + pr) * K + k0 + pc);
        cp_commit();
    };

    int32_t hh[2][4][4], xx[2][4][4];
    #pragma unroll
    for (int i = 0; i < 2; i++)
        #pragma unroll
        for (int j = 0; j < 4; j++)
            #pragma unroll
            for (int u = 0; u < 4; u++) { hh[i][j][u] = 0; xx[i][j][u] = 0; }

    const int KT = K / IBK;
    issue(0, 0);
    issue(1, IBK);

    for (int kt = 0; kt < KT; kt++) {
        if (kt == KT - 1) cp_wait<0>(); else cp_wait<1>();
        __syncthreads();
        const uint32_t base = smB + (uint32_t)(kt & 1) * ISTG;

        #pragma unroll
        for (int ks = 0; ks < 2; ks++) {
            uint32_t a1f[2][4], a2f[2][4];
            #pragma unroll
            for (int i = 0; i < 2; i++) {
                uint32_t ad = base + (uint32_t)((wm + i*16 + (lane & 15)) * IST
                              + ((lane >> 4) * 16) + ks * 32);
                ldsm_x4(a1f[i][0], a1f[i][1], a1f[i][2], a1f[i][3], ad);
                ldsm_x4(a2f[i][0], a2f[i][1], a2f[i][2], a2f[i][3], ad + ITILE);
            }
            uint32_t b1f[4][2], b2f[4][2];
            #pragma unroll
            for (int j = 0; j < 4; j++) {
                uint32_t bd = base + 2 * ITILE + (uint32_t)((wn + j*8 + (lane & 7)) * IST
                              + (((lane & 15) >> 3) * 16) + ks * 32);
                ldsm_x2(b1f[j][0], b1f[j][1], bd);
                ldsm_x2(b2f[j][0], b2f[j][1], bd + ITILE);
            }
            #pragma unroll
            for (int i = 0; i < 2; i++)
                #pragma unroll
                for (int j = 0; j < 4; j++) {
                    imma16832(hh[i][j], a1f[i], b1f[j]);
                    imma16832(xx[i][j], a1f[i], b2f[j]);
                    imma16832(xx[i][j], a2f[i], b1f[j]);
                }
        }
        __syncthreads();
        if (kt + 2 < KT) issue(kt & 1, (kt + 2) * IBK);
    }

    const int g = lane >> 2, tg = lane & 3;
    const float r254 = 1.0f / 254.0f;
    #pragma unroll
    for (int i = 0; i < 2; i++) {
        const int ra = bm0 + wm + i * 16 + g;
        const float sa0 = sA[ra], sa1 = sA[ra + 8];
        #pragma unroll
        for (int j = 0; j < 4; j++) {
            const int c0 = bn0 + wn + j * 8 + tg * 2;
            const float sb0 = sB[c0], sb1 = sB[c0 + 1];
            float f00 = sa0 * sb0 * ((float)hh[i][j][0] + (float)xx[i][j][0] * r254);
            float f01 = sa0 * sb1 * ((float)hh[i][j][1] + (float)xx[i][j][1] * r254);
            float f10 = sa1 * sb0 * ((float)hh[i][j][2] + (float)xx[i][j][2] * r254);
            float f11 = sa1 * sb1 * ((float)hh[i][j][3] + (float)xx[i][j][3] * r254);
            if (OUTMODE == 0) {
                *(float2*)&Cf[(size_t)ra * N + c0]       = make_float2(f00, f01);
                *(float2*)&Cf[(size_t)(ra + 8) * N + c0] = make_float2(f10, f11);
            } else {
                *(uint32_t*)&Ch[(size_t)ra * N + c0]       = pack_hi2(f00, f01);
                *(uint32_t*)&Cl[(size_t)ra * N + c0]       = pack_lo2(f00, f01);
                *(uint32_t*)&Ch[(size_t)(ra + 8) * N + c0] = pack_hi2(f10, f11);
                *(uint32_t*)&Cl[(size_t)(ra + 8) * N + c0] = pack_lo2(f10, f11);
            }
        }
    }
}

__global__ __launch_bounds__(512, 1) void igemm_f32(
    const int8_t* A1, const int8_t* A2, const float* sA,
    const int8_t* B1, const int8_t* B2, const float* sB,
    float* C, int N, int K)
{
    igemm_body<0>(A1, A2, sA, B1, B2, sB, C, nullptr, nullptr, N, K,
                  blockIdx.y * 128, blockIdx.x * 128);
}

__global__ __launch_bounds__(512, 1) void igemm_kv(
    const int8_t* A1, const int8_t* A2, const float* sA,
    const int8_t* K1, const int8_t* K2, const float* sK,
    const int8_t* V1, const int8_t* V2, const float* sV,
    float* ck, __nv_bfloat16* cvh, __nv_bfloat16* cvl)
{
    if (blockIdx.z == 0)
        igemm_body<0>(A1, A2, sA, K1, K2, sK, ck, nullptr, nullptr, KV, C_,
                      blockIdx.y * 128, blockIdx.x * 128);
    else
        igemm_body<1>(A1, A2, sA, V1, V2, sV, nullptr, cvh, cvl, KV, C_,
                      blockIdx.y * 128, blockIdx.x * 128);
}

// ---------------------------------------------------------------------------
// Fused RMSNorm + RoPE; reads fp32, writes split bf16.
// ---------------------------------------------------------------------------
__global__ void rmsrope_kernel(const float* __restrict__ buf,
                               __nv_bfloat16* __restrict__ oh, __nv_bfloat16* __restrict__ ol,
                               int D, float scale) {
    __shared__ float s_x[2048];
    __shared__ float s_wred[8];

    const int row = blockIdx.x;
    const int t = row % T_;
    const int tid = threadIdx.x;
    const int lane = tid & 31;
    const int warp = tid >> 5;
    const float* rp = buf + (size_t)row * D;

    float ss = 0.f;
    for (int d = tid; d < D; d += 256) {
        float v = rp[d];
        s_x[d] = v;
        ss = fmaf(v, v, ss);
    }
    #pragma unroll
    for (int off = 16; off > 0; off >>= 1)
        ss += __shfl_xor_sync(0xffffffffu, ss, off);
    if (lane == 0) s_wred[warp] = ss;
    __syncthreads();
    float tot = 0.f;
    #pragma unroll
    for (int w = 0; w < 8; w++) tot += s_wred[w];
    const float inv = rsqrtf(tot / (float)D + 1e-6f) * scale;

    for (int d = tid; d < D; d += 256) {
        int h = d & 127;
        int i = h & 63;
        float fraction = (float)i * (1.0f / 64.0f);
        float inv_freq = powf(10000.0f, -fraction);
        float ang = (float)t * inv_freq;
        float sv = sinf(ang), cv = cosf(ang);
        float xn = s_x[d] * inv;
        float partner = (h < 64) ? s_x[d + 64] : s_x[d - 64];
        partner *= inv;
        float val = (h < 64) ? fmaf(xn, cv, -partner * sv)
                             : fmaf(xn, cv,  partner * sv);
        __nv_bfloat16 hh = __float2bfloat16(val);
        oh[(size_t)row * D + d] = hh;
        ol[(size_t)row * D + d] = __float2bfloat16(val - __bfloat162float(hh));
    }
}

// ---------------------------------------------------------------------------
// Tensor-core flash attention (bf16x3 mma.sync), fp32 enc output.
// ---------------------------------------------------------------------------
#define BQ 128
#define BK 64
#define QS 136

#define AQ_H 0
#define AQ_L (BQ*QS)
#define AKV_BASE (2*BQ*QS)
#define AKV_STG (4*BK*QS)
#define AK_H(st) (AKV_BASE + (st)*AKV_STG)
#define AK_L(st) (AK_H(st) + BK*QS)
#define AV_H(st) (AK_H(st) + 2*BK*QS)
#define AV_L(st) (AK_H(st) + 3*BK*QS)
#define ATTN_SMEM ((AKV_BASE + 2*AKV_STG) * 2)

__global__ __launch_bounds__(256, 1) void attn_mma(
    const __nv_bfloat16* __restrict__ qhp, const __nv_bfloat16* __restrict__ qlp,
    const __nv_bfloat16* __restrict__ khp, const __nv_bfloat16* __restrict__ klp,
    const __nv_bfloat16* __restrict__ vhp, const __nv_bfloat16* __restrict__ vlp,
    float* __restrict__ enc)
{
    extern __shared__ __nv_bfloat16 sm[];
    const uint32_t smB = (uint32_t)__cvta_generic_to_shared(sm);
    const int tid = threadIdx.x;
    const int lane = tid & 31;
    const int warp = tid >> 5;
    const int b = blockIdx.z;
    const int n = blockIdx.y;
    const int khead = n >> 2;
    const int t0 = blockIdx.x * BQ;

    auto issueQ = [&]() {
        #pragma unroll
        for (int j = 0; j < 8; j++) {
            int i = tid + j * 256;
            int row = i >> 4, c = (i & 15) * 8;
            size_t goff = ((size_t)(b * T_ + t0 + row) * C_) + n * H_ + c;
            cp16(smB + (uint32_t)(AQ_H + row * QS + c) * 2, qhp + goff);
            cp16(smB + (uint32_t)(AQ_L + row * QS + c) * 2, qlp + goff);
        }
    };
    auto issueKV = [&](int st, int s0) {
        #pragma unroll
        for (int j = 0; j < 4; j++) {
            int i = tid + j * 256;
            int row = i >> 4, c = (i & 15) * 8;
            size_t goff = ((size_t)(b * T_ + s0 + row) * KV) + khead * H_ + c;
            cp16(smB + (uint32_t)(AK_H(st) + row * QS + c) * 2, khp + goff);
            cp16(smB + (uint32_t)(AK_L(st) + row * QS + c) * 2, klp + goff);
            cp16(smB + (uint32_t)(AV_H(st) + row * QS + c) * 2, vhp + goff);
            cp16(smB + (uint32_t)(AV_L(st) + row * QS + c) * 2, vlp + goff);
        }
        cp_commit();
    };

    issueQ();
    issueKV(0, 0);
    issueKV(1, BK);

    const int g = lane >> 2, tg = lane & 3;
    float m0 = -INFINITY, m1 = -INFINITY, l0 = 0.f, l1 = 0.f;
    float o[16][4];
    #pragma unroll
    for (int nn = 0; nn < 16; nn++)
        #pragma unroll
        for (int u = 0; u < 4; u++) o[nn][u] = 0.f;

    const int NT = T_ / BK;
    for (int stile = 0; stile < NT; stile++) {
        if (stile == NT - 1) cp_wait<0>(); else cp_wait<1>();
        __syncthreads();
        const int st = stile & 1;

        float s[8][4];
        #pragma unroll
        for (int j = 0; j < 8; j++)
            #pragma unroll
            for (int u = 0; u < 4; u++) s[j][u] = 0.f;

        #pragma unroll
        for (int ks = 0; ks < 8; ks++) {
            uint32_t qh[4], ql[4];
            uint32_t qrow = (uint32_t)(warp * 16 + (lane & 15));
            uint32_t qcol = (uint32_t)(ks * 16 + ((lane >> 4) << 3));
            ldsm_x4(qh[0], qh[1], qh[2], qh[3], smB + (uint32_t)(AQ_H + qrow * QS + qcol) * 2);
            ldsm_x4(ql[0], ql[1], ql[2], ql[3], smB + (uint32_t)(AQ_L + qrow * QS + qcol) * 2);
            #pragma unroll
            for (int j = 0; j < 8; j++) {
                uint32_t kh2[2], kl2[2];
                uint32_t krow = (uint32_t)(j * 8 + (lane & 7));
                uint32_t kcol = (uint32_t)(ks * 16 + (((lane & 15) >> 3) << 3));
                ldsm_x2(kh2[0], kh2[1], smB + (uint32_t)(AK_H(st) + krow * QS + kcol) * 2);
                ldsm_x2(kl2[0], kl2[1], smB + (uint32_t)(AK_L(st) + krow * QS + kcol) * 2);
                mma16816(s[j], qh, kh2);
                mma16816(s[j], ql, kh2);
                mma16816(s[j], qh, kl2);
            }
        }

        float mx0 = -INFINITY, mx1 = -INFINITY;
        #pragma unroll
        for (int j = 0; j < 8; j++) {
            mx0 = fmaxf(mx0, fmaxf(s[j][0], s[j][1]));
            mx1 = fmaxf(mx1, fmaxf(s[j][2], s[j][3]));
        }
        mx0 = fmaxf(mx0, __shfl_xor_sync(0xffffffffu, mx0, 1));
        mx0 = fmaxf(mx0, __shfl_xor_sync(0xffffffffu, mx0, 2));
        mx1 = fmaxf(mx1, __shfl_xor_sync(0xffffffffu, mx1, 1));
        mx1 = fmaxf(mx1, __shfl_xor_sync(0xffffffffu, mx1, 2));
        float m0n = fmaxf(m0, mx0);
        float m1n = fmaxf(m1, mx1);
        float a0 = __expf(m0 - m0n);
        float a1 = __expf(m1 - m1n);
        float sum0 = 0.f, sum1 = 0.f;
        #pragma unroll
        for (int j = 0; j < 8; j++) {
            s[j][0] = __expf(s[j][0] - m0n);
            s[j][1] = __expf(s[j][1] - m0n);
            s[j][2] = __expf(s[j][2] - m1n);
            s[j][3] = __expf(s[j][3] - m1n);
            sum0 += s[j][0] + s[j][1];
            sum1 += s[j][2] + s[j][3];
        }
        sum0 += __shfl_xor_sync(0xffffffffu, sum0, 1);
        sum0 += __shfl_xor_sync(0xffffffffu, sum0, 2);
        sum1 += __shfl_xor_sync(0xffffffffu, sum1, 1);
        sum1 += __shfl_xor_sync(0xffffffffu, sum1, 2);
        l0 = l0 * a0 + sum0;
        l1 = l1 * a1 + sum1;
        m0 = m0n; m1 = m1n;
        #pragma unroll
        for (int nn = 0; nn < 16; nn++) {
            o[nn][0] *= a0; o[nn][1] *= a0;
            o[nn][2] *= a1; o[nn][3] *= a1;
        }

        #pragma unroll
        for (int kk = 0; kk < 4; kk++) {
            const int j0 = kk * 2;
            uint32_t ah[4], al[4];
            ah[0] = pack_hi2(s[j0][0],   s[j0][1]);
            ah[1] = pack_hi2(s[j0][2],   s[j0][3]);
            ah[2] = pack_hi2(s[j0+1][0], s[j0+1][1]);
            ah[3] = pack_hi2(s[j0+1][2], s[j0+1][3]);
            al[0] = pack_lo2(s[j0][0],   s[j0][1]);
            al[1] = pack_lo2(s[j0][2],   s[j0][3]);
            al[2] = pack_lo2(s[j0+1][0], s[j0+1][1]);
            al[3] = pack_lo2(s[j0+1][2], s[j0+1][3]);
            #pragma unroll
            for (int nn = 0; nn < 16; nn++) {
                uint32_t bh2[2], bl2[2];
                uint32_t vrow = (uint32_t)(kk * 16 + (lane & 15));
                ldsm_x2t(bh2[0], bh2[1], smB + (uint32_t)(AV_H(st) + vrow * QS + nn * 8) * 2);
                ldsm_x2t(bl2[0], bl2[1], smB + (uint32_t)(AV_L(st) + vrow * QS + nn * 8) * 2);
                mma16816(o[nn], ah, bh2);
                mma16816(o[nn], al, bh2);
                mma16816(o[nn], ah, bl2);
            }
        }

        __syncthreads();
        if (stile + 2 < NT) issueKV(st, (stile + 2) * BK);
    }

    float il0 = 1.0f / l0;
    float il1 = 1.0f / l1;
    const int r0 = t0 + warp * 16 + g;
    #pragma unroll
    for (int nn = 0; nn < 16; nn++) {
        int c0 = nn * 8 + tg * 2;
        size_t base0 = ((size_t)(b * T_ + r0) * C_) + n * H_ + c0;
        size_t base1 = ((size_t)(b * T_ + r0 + 8) * C_) + n * H_ + c0;
        *(float2*)&enc[base0] = make_float2(o[nn][0] * il0, o[nn][1] * il0);
        *(float2*)&enc[base1] = make_float2(o[nn][2] * il1, o[nn][3] * il1);
    }
}

// ---------------------------------------------------------------------------
extern "C" void kernel_launch(void* const* d_in, const int* in_sizes, int n_in,
                              void* d_out, int out_size) {
    const float* x  = (const float*)d_in[0];
    const float* wq = (const float*)d_in[1];
    const float* wk = (const float*)d_in[2];
    const float* wv = (const float*)d_in[3];
    const float* wo = (const float*)d_in[4];
    float* out = (float*)d_out;

    float *gq, *gk, *genc, *sx, *swq, *swk, *swv, *swo, *se;
    int8_t *xq1,*xq2,*wqq1,*wqq2,*wkq1,*wkq2,*wvq1,*wvq2,*woq1,*woq2,*eq1,*eq2;
    __nv_bfloat16 *qh,*ql,*kh,*kl,*vh,*vl;
    cudaGetSymbolAddress((void**)&gq, g_q);
    cudaGetSymbolAddress((void**)&gk, g_k);
    cudaGetSymbolAddress((void**)&genc, g_enc);
    cudaGetSymbolAddress((void**)&xq1, g_xq1);   cudaGetSymbolAddress((void**)&xq2, g_xq2);
    cudaGetSymbolAddress((void**)&sx, g_sx);
    cudaGetSymbolAddress((void**)&wqq1, g_wqq1); cudaGetSymbolAddress((void**)&wqq2, g_wqq2);
    cudaGetSymbolAddress((void**)&swq, g_swq);
    cudaGetSymbolAddress((void**)&wkq1, g_wkq1); cudaGetSymbolAddress((void**)&wkq2, g_wkq2);
    cudaGetSymbolAddress((void**)&swk, g_swk);
    cudaGetSymbolAddress((void**)&wvq1, g_wvq1); cudaGetSymbolAddress((void**)&wvq2, g_wvq2);
    cudaGetSymbolAddress((void**)&swv, g_swv);
    cudaGetSymbolAddress((void**)&woq1, g_woq1); cudaGetSymbolAddress((void**)&woq2, g_woq2);
    cudaGetSymbolAddress((void**)&swo, g_swo);
    cudaGetSymbolAddress((void**)&eq1, g_eq1);   cudaGetSymbolAddress((void**)&eq2, g_eq2);
    cudaGetSymbolAddress((void**)&se, g_se);
    cudaGetSymbolAddress((void**)&qh, g_qh);     cudaGetSymbolAddress((void**)&ql, g_ql);
    cudaGetSymbolAddress((void**)&kh, g_kh);     cudaGetSymbolAddress((void**)&kl, g_kl);
    cudaGetSymbolAddress((void**)&vh, g_vh);     cudaGetSymbolAddress((void**)&vl, g_vl);

    cudaFuncSetAttribute(igemm_f32, cudaFuncAttributeMaxDynamicSharedMemorySize, IG_SMEM);
    cudaFuncSetAttribute(igemm_kv,  cudaFuncAttributeMaxDynamicSharedMemorySize, IG_SMEM);
    cudaFuncSetAttribute(attn_mma,  cudaFuncAttributeMaxDynamicSharedMemorySize, ATTN_SMEM);

    // quantize x and weights
    quant_rows<<<M_, 256>>>(x, xq1, xq2, sx, C_);
    colmax<<<C_/256, 256>>>(wq, swq, C_, C_);
    tquant<<<dim3(C_/32, C_/32), dim3(32,8)>>>(wq, swq, wqq1, wqq2, C_, C_);
    colmax<<<KV/256, 256>>>(wk, swk, C_, KV);
    tquant<<<dim3(KV/32, C_/32), dim3(32,8)>>>(wk, swk, wkq1, wkq2, C_, KV);
    colmax<<<KV/256, 256>>>(wv, swv, C_, KV);
    tquant<<<dim3(KV/32, C_/32), dim3(32,8)>>>(wv, swv, wvq1, wvq2, C_, KV);
    colmax<<<C_/256, 256>>>(wo, swo, C_, C_);
    tquant<<<dim3(C_/32, C_/32), dim3(32,8)>>>(wo, swo, woq1, woq2, C_, C_);

    // projections (int8 tensor cores)
    igemm_f32<<<dim3(C_/128, M_/128), 512, IG_SMEM>>>(xq1, xq2, sx, wqq1, wqq2, swq, gq, C_, C_);
    igemm_kv<<<dim3(KV/128, M_/128, 2), 512, IG_SMEM>>>(xq1, xq2, sx,
                                                        wkq1, wkq2, swk,
                                                        wvq1, wvq2, swv,
                                                        gk, vh, vl);

    // rmsnorm + rope -> split bf16
    const float qscale = 0.08838834764831845f;  // 1/sqrt(128)
    rmsrope_kernel<<<M_, 256>>>(gq, qh, ql, C_, qscale);
    rmsrope_kernel<<<M_, 256>>>(gk, kh, kl, KV, 1.0f);

    // flash attention (bf16x3) -> fp32 enc
    attn_mma<<<dim3(T_/BQ, NH, B_), 256, ATTN_SMEM>>>(qh, ql, kh, kl, vh, vl, genc);

    // quantize enc, output projection (int8)
    quant_rows<<<M_, 256>>>(genc, eq1, eq2, se, C_);
    igemm_f32<<<dim3(C_/128, M_/128), 512, IG_SMEM>>>(eq1, eq2, se, woq1, woq2, swo, out, C_, C_);
}

// round 10
// speedup vs baseline: 1.0056x; 1.0056x over previous
#include <cuda_runtime.h>
#include <cuda_bf16.h>
#include <math.h>
#include <stdint.h>

#define B_  2
#define T_  1024
#define C_  2048
#define NH  16
#define KH  4
#define H_  128
#define M_  (B_*T_)
#define KV  (KH*H_)     // 512

// fp32 scratch
__device__ float g_q[M_ * C_];
__device__ float g_k[M_ * KV];
__device__ float g_enc[M_ * C_];
// int8 quantized operands (digit1, digit2) + per-row scales
__device__ int8_t g_xq1[M_*C_],  g_xq2[M_*C_];
__device__ float  g_sx[M_];
__device__ int8_t g_wqq1[C_*C_], g_wqq2[C_*C_];   // [N,K]
__device__ float  g_swq[C_];
__device__ int8_t g_wkq1[KV*C_], g_wkq2[KV*C_];
__device__ float  g_swk[KV];
__device__ int8_t g_wvq1[KV*C_], g_wvq2[KV*C_];
__device__ float  g_swv[KV];
__device__ int8_t g_woq1[C_*C_], g_woq2[C_*C_];
__device__ float  g_swo[C_];
__device__ int8_t g_eq1[M_*C_],  g_eq2[M_*C_];
__device__ float  g_se[M_];
// bf16 split operands for attention
__device__ __nv_bfloat16 g_qh[M_*C_],  g_ql[M_*C_];
__device__ __nv_bfloat16 g_kh[M_*KV],  g_kl[M_*KV];
__device__ __nv_bfloat16 g_vh[M_*KV],  g_vl[M_*KV];

// ---------------- helpers ----------------
__device__ __forceinline__ void ldsm_x4(uint32_t& r0, uint32_t& r1, uint32_t& r2,
                                        uint32_t& r3, uint32_t addr) {
    asm volatile("ldmatrix.sync.aligned.m8n8.x4.shared.b16 {%0,%1,%2,%3}, [%4];"
                 : "=r"(r0), "=r"(r1), "=r"(r2), "=r"(r3) : "r"(addr));
}
__device__ __forceinline__ void ldsm_x2(uint32_t& r0, uint32_t& r1, uint32_t addr) {
    asm volatile("ldmatrix.sync.aligned.m8n8.x2.shared.b16 {%0,%1}, [%2];"
                 : "=r"(r0), "=r"(r1) : "r"(addr));
}
__device__ __forceinline__ void ldsm_x2t(uint32_t& r0, uint32_t& r1, uint32_t addr) {
    asm volatile("ldmatrix.sync.aligned.m8n8.x2.trans.shared.b16 {%0,%1}, [%2];"
                 : "=r"(r0), "=r"(r1) : "r"(addr));
}
__device__ __forceinline__ void mma16816(float* c, const uint32_t* a, const uint32_t* b) {
    asm volatile("mma.sync.aligned.m16n8k16.row.col.f32.bf16.bf16.f32 "
                 "{%0,%1,%2,%3}, {%4,%5,%6,%7}, {%8,%9}, {%0,%1,%2,%3};"
                 : "+f"(c[0]), "+f"(c[1]), "+f"(c[2]), "+f"(c[3])
                 : "r"(a[0]), "r"(a[1]), "r"(a[2]), "r"(a[3]), "r"(b[0]), "r"(b[1]));
}
__device__ __forceinline__ void imma16832(int32_t* c, const uint32_t* a, const uint32_t* b) {
    asm volatile("mma.sync.aligned.m16n8k32.row.col.s32.s8.s8.s32 "
                 "{%0,%1,%2,%3}, {%4,%5,%6,%7}, {%8,%9}, {%0,%1,%2,%3};"
                 : "+r"(c[0]), "+r"(c[1]), "+r"(c[2]), "+r"(c[3])
                 : "r"(a[0]), "r"(a[1]), "r"(a[2]), "r"(a[3]), "r"(b[0]), "r"(b[1]));
}
__device__ __forceinline__ uint32_t pack_bf2(__nv_bfloat16 a, __nv_bfloat16 b) {
    __nv_bfloat162 t = __halves2bfloat162(a, b);
    return *reinterpret_cast<uint32_t*>(&t);
}
__device__ __forceinline__ uint32_t pack_hi2(float x, float y) {
    return pack_bf2(__float2bfloat16(x), __float2bfloat16(y));
}
__device__ __forceinline__ uint32_t pack_lo2(float x, float y) {
    __nv_bfloat16 hx = __float2bfloat16(x), hy = __float2bfloat16(y);
    return pack_bf2(__float2bfloat16(x - __bfloat162float(hx)),
                    __float2bfloat16(y - __bfloat162float(hy)));
}
__device__ __forceinline__ void cp16(uint32_t s, const void* g) {
    asm volatile("cp.async.cg.shared.global [%0], [%1], 16;" :: "r"(s), "l"(g));
}
__device__ __forceinline__ void cp_commit() { asm volatile("cp.async.commit_group;"); }
template<int N> __device__ __forceinline__ void cp_wait() {
    asm volatile("cp.async.wait_group %0;" :: "n"(N));
}
__device__ __forceinline__ uint32_t smem_u32(const void* p) {
    return (uint32_t)__cvta_generic_to_shared(p);
}

// ---------------------------------------------------------------------------
// Row quantization: per row of [rows, D]: s = max|x|/127; a1=rint(x/s),
// a2=rint((x/s-a1)*254). One block per row.
// ---------------------------------------------------------------------------
__global__ void quant_rows(const float* __restrict__ in, int8_t* __restrict__ q1,
                           int8_t* __restrict__ q2, float* __restrict__ sc, int D) {
    __shared__ float sx[2048];
    __shared__ float swr[8];
    const int row = blockIdx.x;
    const int tid = threadIdx.x;
    const int lane = tid & 31, warp = tid >> 5;
    const float* rp = in + (size_t)row * D;

    float m = 0.f;
    for (int d = tid; d < D; d += 256) {
        float v = rp[d];
        sx[d] = v;
        m = fmaxf(m, fabsf(v));
    }
    #pragma unroll
    for (int off = 16; off > 0; off >>= 1)
        m = fmaxf(m, __shfl_xor_sync(0xffffffffu, m, off));
    if (lane == 0) swr[warp] = m;
    __syncthreads();
    float tot = 0.f;
    #pragma unroll
    for (int w = 0; w < 8; w++) tot = fmaxf(tot, swr[w]);
    const float s = fmaxf(tot, 1e-20f) * (1.0f / 127.0f);
    const float inv = 1.0f / s;
    if (tid == 0) sc[row] = s;

    for (int d = tid; d < D; d += 256) {
        float v = sx[d] * inv;
        float a1 = rintf(v);
        float a2 = rintf((v - a1) * 254.0f);
        q1[(size_t)row * D + d] = (int8_t)(int)a1;
        q2[(size_t)row * D + d] = (int8_t)(int)a2;
    }
}

// Column max of W[K,N] -> sB[n] = max/127
__global__ void colmax(const float* __restrict__ W, float* __restrict__ sB, int K, int N) {
    int n = blockIdx.x * 256 + threadIdx.x;
    if (n < N) {
        float m = 0.f;
        for (int k = 0; k < K; k++) m = fmaxf(m, fabsf(W[(size_t)k * N + n]));
        sB[n] = fmaxf(m, 1e-20f) * (1.0f / 127.0f);
    }
}

// Transpose + quantize: W[K,N] fp32 -> q1/q2[N,K] s8 using sB[n]
__global__ void tquant(const float* __restrict__ W, const float* __restrict__ sB,
                       int8_t* __restrict__ q1, int8_t* __restrict__ q2, int K, int N) {
    __shared__ float t[32][33];
    const int n0 = blockIdx.x * 32, k0 = blockIdx.y * 32;
    const int tx = threadIdx.x, ty = threadIdx.y;
    #pragma unroll
    for (int i = 0; i < 4; i++)
        t[ty + i * 8][tx] = W[(size_t)(k0 + ty + i * 8) * N + n0 + tx];
    __syncthreads();
    #pragma unroll
    for (int i = 0; i < 4; i++) {
        int n = n0 + ty + i * 8;
        float inv = 1.0f / sB[n];
        float v = t[tx][ty + i * 8] * inv;
        float a1 = rintf(v);
        float a2 = rintf((v - a1) * 254.0f);
        size_t o = (size_t)n * K + k0 + tx;
        q1[o] = (int8_t)(int)a1;
        q2[o] = (int8_t)(int)a2;
    }
}

// ---------------------------------------------------------------------------
// INT8 two-digit GEMM: C[M,N] = (sA*sB) * (S11 + S12/254), tile 128x128,
// BK=64, 512 threads (4x4 warps, warp tile 32x32), 2-stage cp.async.
// ---------------------------------------------------------------------------
#define IBK  64
#define IST  80                 // bytes per smem row slot (conflict-free)
#define ITILE (128*IST)         // 10240 B
#define ISTG (4*ITILE)          // A1,A2,B1,B2 per stage
#define IG_SMEM (2*ISTG)        // 81920 B

template<int OUTMODE>   // 0: fp32, 1: split bf16
__device__ __forceinline__ void igemm_body(
    const int8_t* __restrict__ A1, const int8_t* __restrict__ A2, const float* __restrict__ sA,
    const int8_t* __restrict__ B1, const int8_t* __restrict__ B2, const float* __restrict__ sB,
    float* __restrict__ Cf, __nv_bfloat16* __restrict__ Ch, __nv_bfloat16* __restrict__ Cl,
    int N, int K, int bm0, int bn0)
{
    extern __shared__ int8_t ism[];
    const uint32_t smB = smem_u32(ism);
    const int tid = threadIdx.x;
    const int lane = tid & 31;
    const int warp = tid >> 5;
    const int wm = (warp >> 2) * 32;
    const int wn = (warp & 3) * 32;

    const int pr = tid >> 2, pc = (tid & 3) * 16;

    auto issue = [&](int st, int k0) {
        uint32_t s0 = smB + (uint32_t)st * ISTG + (uint32_t)pr * IST + pc;
        cp16(s0,             A1 + (size_t)(bm0 + pr) * K + k0 + pc);
        cp16(s0 + ITILE,     A2 + (size_t)(bm0 + pr) * K + k0 + pc);
        cp16(s0 + 2 * ITILE, B1 + (size_t)(bn0 + pr) * K + k0 + pc);
        cp16(s0 + 3 * ITILE, B2 + (size_t)(bn0 + pr) * K + k0 + pc);
        cp_commit();
    };

    int32_t hh[2][4][4], xx[2][4][4];
    #pragma unroll
    for (int i = 0; i < 2; i++)
        #pragma unroll
        for (int j = 0; j < 4; j++)
            #pragma unroll
            for (int u = 0; u < 4; u++) { hh[i][j][u] = 0; xx[i][j][u] = 0; }

    const int KT = K / IBK;
    issue(0, 0);
    issue(1, IBK);

    for (int kt = 0; kt < KT; kt++) {
        if (kt == KT - 1) cp_wait<0>(); else cp_wait<1>();
        __syncthreads();
        const uint32_t base = smB + (uint32_t)(kt & 1) * ISTG;

        #pragma unroll
        for (int ks = 0; ks < 2; ks++) {
            uint32_t a1f[2][4], a2f[2][4];
            #pragma unroll
            for (int i = 0; i < 2; i++) {
                uint32_t ad = base + (uint32_t)((wm + i*16 + (lane & 15)) * IST
                              + ((lane >> 4) * 16) + ks * 32);
                ldsm_x4(a1f[i][0], a1f[i][1], a1f[i][2], a1f[i][3], ad);
                ldsm_x4(a2f[i][0], a2f[i][1], a2f[i][2], a2f[i][3], ad + ITILE);
            }
            uint32_t b1f[4][2], b2f[4][2];
            #pragma unroll
            for (int j = 0; j < 4; j++) {
                uint32_t bd = base + 2 * ITILE + (uint32_t)((wn + j*8 + (lane & 7)) * IST
                              + (((lane & 15) >> 3) * 16) + ks * 32);
                ldsm_x2(b1f[j][0], b1f[j][1], bd);
                ldsm_x2(b2f[j][0], b2f[j][1], bd + ITILE);
            }
            #pragma unroll
            for (int i = 0; i < 2; i++)
                #pragma unroll
                for (int j = 0; j < 4; j++) {
                    imma16832(hh[i][j], a1f[i], b1f[j]);
                    imma16832(xx[i][j], a1f[i], b2f[j]);
                    imma16832(xx[i][j], a2f[i], b1f[j]);
                }
        }
        __syncthreads();
        if (kt + 2 < KT) issue(kt & 1, (kt + 2) * IBK);
    }

    const int g = lane >> 2, tg = lane & 3;
    const float r254 = 1.0f / 254.0f;
    #pragma unroll
    for (int i = 0; i < 2; i++) {
        const int ra = bm0 + wm + i * 16 + g;
        const float sa0 = sA[ra], sa1 = sA[ra + 8];
        #pragma unroll
        for (int j = 0; j < 4; j++) {
            const int c0 = bn0 + wn + j * 8 + tg * 2;
            const float sb0 = sB[c0], sb1 = sB[c0 + 1];
            float f00 = sa0 * sb0 * ((float)hh[i][j][0] + (float)xx[i][j][0] * r254);
            float f01 = sa0 * sb1 * ((float)hh[i][j][1] + (float)xx[i][j][1] * r254);
            float f10 = sa1 * sb0 * ((float)hh[i][j][2] + (float)xx[i][j][2] * r254);
            float f11 = sa1 * sb1 * ((float)hh[i][j][3] + (float)xx[i][j][3] * r254);
            if (OUTMODE == 0) {
                *(float2*)&Cf[(size_t)ra * N + c0]       = make_float2(f00, f01);
                *(float2*)&Cf[(size_t)(ra + 8) * N + c0] = make_float2(f10, f11);
            } else {
                *(uint32_t*)&Ch[(size_t)ra * N + c0]       = pack_hi2(f00, f01);
                *(uint32_t*)&Cl[(size_t)ra * N + c0]       = pack_lo2(f00, f01);
                *(uint32_t*)&Ch[(size_t)(ra + 8) * N + c0] = pack_hi2(f10, f11);
                *(uint32_t*)&Cl[(size_t)(ra + 8) * N + c0] = pack_lo2(f10, f11);
            }
        }
    }
}

__global__ __launch_bounds__(512, 1) void igemm_f32(
    const int8_t* A1, const int8_t* A2, const float* sA,
    const int8_t* B1, const int8_t* B2, const float* sB,
    float* C, int N, int K)
{
    igemm_body<0>(A1, A2, sA, B1, B2, sB, C, nullptr, nullptr, N, K,
                  blockIdx.y * 128, blockIdx.x * 128);
}

__global__ __launch_bounds__(512, 1) void igemm_kv(
    const int8_t* A1, const int8_t* A2, const float* sA,
    const int8_t* K1, const int8_t* K2, const float* sK,
    const int8_t* V1, const int8_t* V2, const float* sV,
    float* ck, __nv_bfloat16* cvh, __nv_bfloat16* cvl)
{
    if (blockIdx.z == 0)
        igemm_body<0>(A1, A2, sA, K1, K2, sK, ck, nullptr, nullptr, KV, C_,
                      blockIdx.y * 128, blockIdx.x * 128);
    else
        igemm_body<1>(A1, A2, sA, V1, V2, sV, nullptr, cvh, cvl, KV, C_,
                      blockIdx.y * 128, blockIdx.x * 128);
}

// ---------------------------------------------------------------------------
// Fused RMSNorm + RoPE; reads fp32, writes split bf16.
// ---------------------------------------------------------------------------
__global__ void rmsrope_kernel(const float* __restrict__ buf,
                               __nv_bfloat16* __restrict__ oh, __nv_bfloat16* __restrict__ ol,
                               int D, float scale) {
    __shared__ float s_x[2048];
    __shared__ float s_wred[8];

    const int row = blockIdx.x;
    const int t = row % T_;
    const int tid = threadIdx.x;
    const int lane = tid & 31;
    const int warp = tid >> 5;
    const float* rp = buf + (size_t)row * D;

    float ss = 0.f;
    for (int d = tid; d < D; d += 256) {
        float v = rp[d];
        s_x[d] = v;
        ss = fmaf(v, v, ss);
    }
    #pragma unroll
    for (int off = 16; off > 0; off >>= 1)
        ss += __shfl_xor_sync(0xffffffffu, ss, off);
    if (lane == 0) s_wred[warp] = ss;
    __syncthreads();
    float tot = 0.f;
    #pragma unroll
    for (int w = 0; w < 8; w++) tot += s_wred[w];
    const float inv = rsqrtf(tot / (float)D + 1e-6f) * scale;

    for (int d = tid; d < D; d += 256) {
        int h = d & 127;
        int i = h & 63;
        float fraction = (float)i * (1.0f / 64.0f);
        float inv_freq = powf(10000.0f, -fraction);
        float ang = (float)t * inv_freq;
        float sv = sinf(ang), cv = cosf(ang);
        float xn = s_x[d] * inv;
        float partner = (h < 64) ? s_x[d + 64] : s_x[d - 64];
        partner *= inv;
        float val = (h < 64) ? fmaf(xn, cv, -partner * sv)
                             : fmaf(xn, cv,  partner * sv);
        __nv_bfloat16 hh = __float2bfloat16(val);
        oh[(size_t)row * D + d] = hh;
        ol[(size_t)row * D + d] = __float2bfloat16(val - __bfloat162float(hh));
    }
}

// ---------------------------------------------------------------------------
// Tensor-core flash attention (bf16x3 mma.sync), fp32 enc output.
// ---------------------------------------------------------------------------
#define BQ 128
#define BK 64
#define QS 136

#define AQ_H 0
#define AQ_L (BQ*QS)
#define AKV_BASE (2*BQ*QS)
#define AKV_STG (4*BK*QS)
#define AK_H(st) (AKV_BASE + (st)*AKV_STG)
#define AK_L(st) (AK_H(st) + BK*QS)
#define AV_H(st) (AK_H(st) + 2*BK*QS)
#define AV_L(st) (AK_H(st) + 3*BK*QS)
#define ATTN_SMEM ((AKV_BASE + 2*AKV_STG) * 2)

__global__ __launch_bounds__(256, 1) void attn_mma(
    const __nv_bfloat16* __restrict__ qhp, const __nv_bfloat16* __restrict__ qlp,
    const __nv_bfloat16* __restrict__ khp, const __nv_bfloat16* __restrict__ klp,
    const __nv_bfloat16* __restrict__ vhp, const __nv_bfloat16* __restrict__ vlp,
    float* __restrict__ enc)
{
    extern __shared__ __nv_bfloat16 sm[];
    const uint32_t smB = (uint32_t)__cvta_generic_to_shared(sm);
    const int tid = threadIdx.x;
    const int lane = tid & 31;
    const int warp = tid >> 5;
    const int b = blockIdx.z;
    const int n = blockIdx.y;
    const int khead = n >> 2;
    const int t0 = blockIdx.x * BQ;

    auto issueQ = [&]() {
        #pragma unroll
        for (int j = 0; j < 8; j++) {
            int i = tid + j * 256;
            int row = i >> 4, c = (i & 15) * 8;
            size_t goff = ((size_t)(b * T_ + t0 + row) * C_) + n * H_ + c;
            cp16(smB + (uint32_t)(AQ_H + row * QS + c) * 2, qhp + goff);
            cp16(smB + (uint32_t)(AQ_L + row * QS + c) * 2, qlp + goff);
        }
    };
    auto issueKV = [&](int st, int s0) {
        #pragma unroll
        for (int j = 0; j < 4; j++) {
            int i = tid + j * 256;
            int row = i >> 4, c = (i & 15) * 8;
            size_t goff = ((size_t)(b * T_ + s0 + row) * KV) + khead * H_ + c;
            cp16(smB + (uint32_t)(AK_H(st) + row * QS + c) * 2, khp + goff);
            cp16(smB + (uint32_t)(AK_L(st) + row * QS + c) * 2, klp + goff);
            cp16(smB + (uint32_t)(AV_H(st) + row * QS + c) * 2, vhp + goff);
            cp16(smB + (uint32_t)(AV_L(st) + row * QS + c) * 2, vlp + goff);
        }
        cp_commit();
    };

    issueQ();
    issueKV(0, 0);
    issueKV(1, BK);

    const int g = lane >> 2, tg = lane & 3;
    float m0 = -INFINITY, m1 = -INFINITY, l0 = 0.f, l1 = 0.f;
    float o[16][4];
    #pragma unroll
    for (int nn = 0; nn < 16; nn++)
        #pragma unroll
        for (int u = 0; u < 4; u++) o[nn][u] = 0.f;

    const int NT = T_ / BK;
    for (int stile = 0; stile < NT; stile++) {
        if (stile == NT - 1) cp_wait<0>(); else cp_wait<1>();
        __syncthreads();
        const int st = stile & 1;

        float s[8][4];
        #pragma unroll
        for (int j = 0; j < 8; j++)
            #pragma unroll
            for (int u = 0; u < 4; u++) s[j][u] = 0.f;

        #pragma unroll
        for (int ks = 0; ks < 8; ks++) {
            uint32_t qh[4], ql[4];
            uint32_t qrow = (uint32_t)(warp * 16 + (lane & 15));
            uint32_t qcol = (uint32_t)(ks * 16 + ((lane >> 4) << 3));
            ldsm_x4(qh[0], qh[1], qh[2], qh[3], smB + (uint32_t)(AQ_H + qrow * QS + qcol) * 2);
            ldsm_x4(ql[0], ql[1], ql[2], ql[3], smB + (uint32_t)(AQ_L + qrow * QS + qcol) * 2);
            #pragma unroll
            for (int j = 0; j < 8; j++) {
                uint32_t kh2[2], kl2[2];
                uint32_t krow = (uint32_t)(j * 8 + (lane & 7));
                uint32_t kcol = (uint32_t)(ks * 16 + (((lane & 15) >> 3) << 3));
                ldsm_x2(kh2[0], kh2[1], smB + (uint32_t)(AK_H(st) + krow * QS + kcol) * 2);
                ldsm_x2(kl2[0], kl2[1], smB + (uint32_t)(AK_L(st) + krow * QS + kcol) * 2);
                mma16816(s[j], qh, kh2);
                mma16816(s[j], ql, kh2);
                mma16816(s[j], qh, kl2);
            }
        }

        float mx0 = -INFINITY, mx1 = -INFINITY;
        #pragma unroll
        for (int j = 0; j < 8; j++) {
            mx0 = fmaxf(mx0, fmaxf(s[j][0], s[j][1]));
            mx1 = fmaxf(mx1, fmaxf(s[j][2], s[j][3]));
        }
        mx0 = fmaxf(mx0, __shfl_xor_sync(0xffffffffu, mx0, 1));
        mx0 = fmaxf(mx0, __shfl_xor_sync(0xffffffffu, mx0, 2));
        mx1 = fmaxf(mx1, __shfl_xor_sync(0xffffffffu, mx1, 1));
        mx1 = fmaxf(mx1, __shfl_xor_sync(0xffffffffu, mx1, 2));
        float m0n = fmaxf(m0, mx0);
        float m1n = fmaxf(m1, mx1);
        float a0 = __expf(m0 - m0n);
        float a1 = __expf(m1 - m1n);
        float sum0 = 0.f, sum1 = 0.f;
        #pragma unroll
        for (int j = 0; j < 8; j++) {
            s[j][0] = __expf(s[j][0] - m0n);
            s[j][1] = __expf(s[j][1] - m0n);
            s[j][2] = __expf(s[j][2] - m1n);
            s[j][3] = __expf(s[j][3] - m1n);
            sum0 += s[j][0] + s[j][1];
            sum1 += s[j][2] + s[j][3];
        }
        sum0 += __shfl_xor_sync(0xffffffffu, sum0, 1);
        sum0 += __shfl_xor_sync(0xffffffffu, sum0, 2);
        sum1 += __shfl_xor_sync(0xffffffffu, sum1, 1);
        sum1 += __shfl_xor_sync(0xffffffffu, sum1, 2);
        l0 = l0 * a0 + sum0;
        l1 = l1 * a1 + sum1;
        m0 = m0n; m1 = m1n;
        #pragma unroll
        for (int nn = 0; nn < 16; nn++) {
            o[nn][0] *= a0; o[nn][1] *= a0;
            o[nn][2] *= a1; o[nn][3] *= a1;
        }

        #pragma unroll
        for (int kk = 0; kk < 4; kk++) {
            const int j0 = kk * 2;
            uint32_t ah[4], al[4];
            ah[0] = pack_hi2(s[j0][0],   s[j0][1]);
            ah[1] = pack_hi2(s[j0][2],   s[j0][3]);
            ah[2] = pack_hi2(s[j0+1][0], s[j0+1][1]);
            ah[3] = pack_hi2(s[j0+1][2], s[j0+1][3]);
            al[0] = pack_lo2(s[j0][0],   s[j0][1]);
            al[1] = pack_lo2(s[j0][2],   s[j0][3]);
            al[2] = pack_lo2(s[j0+1][0], s[j0+1][1]);
            al[3] = pack_lo2(s[j0+1][2], s[j0+1][3]);
            #pragma unroll
            for (int nn = 0; nn < 16; nn++) {
                uint32_t bh2[2], bl2[2];
                uint32_t vrow = (uint32_t)(kk * 16 + (lane & 15));
                ldsm_x2t(bh2[0], bh2[1], smB + (uint32_t)(AV_H(st) + vrow * QS + nn * 8) * 2);
                ldsm_x2t(bl2[0], bl2[1], smB + (uint32_t)(AV_L(st) + vrow * QS + nn * 8) * 2);
                mma16816(o[nn], ah, bh2);
                mma16816(o[nn], al, bh2);
                mma16816(o[nn], ah, bl2);
            }
        }

        __syncthreads();
        if (stile + 2 < NT) issueKV(st, (stile + 2) * BK);
    }

    float il0 = 1.0f / l0;
    float il1 = 1.0f / l1;
    const int r0 = t0 + warp * 16 + g;
    #pragma unroll
    for (int nn = 0; nn < 16; nn++) {
        int c0 = nn * 8 + tg * 2;
        size_t base0 = ((size_t)(b * T_ + r0) * C_) + n * H_ + c0;
        size_t base1 = ((size_t)(b * T_ + r0 + 8) * C_) + n * H_ + c0;
        *(float2*)&enc[base0] = make_float2(o[nn][0] * il0, o[nn][1] * il0);
        *(float2*)&enc[base1] = make_float2(o[nn][2] * il1, o[nn][3] * il1);
    }
}

// ---------------------------------------------------------------------------
extern "C" void kernel_launch(void* const* d_in, const int* in_sizes, int n_in,
                              void* d_out, int out_size) {
    const float* x  = (const float*)d_in[0];
    const float* wq = (const float*)d_in[1];
    const float* wk = (const float*)d_in[2];
    const float* wv = (const float*)d_in[3];
    const float* wo = (const float*)d_in[4];
    float* out = (float*)d_out;

    float *gq, *gk, *genc, *sx, *swq, *swk, *swv, *swo, *se;
    int8_t *xq1,*xq2,*wqq1,*wqq2,*wkq1,*wkq2,*wvq1,*wvq2,*woq1,*woq2,*eq1,*eq2;
    __nv_bfloat16 *qh,*ql,*kh,*kl,*vh,*vl;
    cudaGetSymbolAddress((void**)&gq, g_q);
    cudaGetSymbolAddress((void**)&gk, g_k);
    cudaGetSymbolAddress((void**)&genc, g_enc);
    cudaGetSymbolAddress((void**)&xq1, g_xq1);   cudaGetSymbolAddress((void**)&xq2, g_xq2);
    cudaGetSymbolAddress((void**)&sx, g_sx);
    cudaGetSymbolAddress((void**)&wqq1, g_wqq1); cudaGetSymbolAddress((void**)&wqq2, g_wqq2);
    cudaGetSymbolAddress((void**)&swq, g_swq);
    cudaGetSymbolAddress((void**)&wkq1, g_wkq1); cudaGetSymbolAddress((void**)&wkq2, g_wkq2);
    cudaGetSymbolAddress((void**)&swk, g_swk);
    cudaGetSymbolAddress((void**)&wvq1, g_wvq1); cudaGetSymbolAddress((void**)&wvq2, g_wvq2);
    cudaGetSymbolAddress((void**)&swv, g_swv);
    cudaGetSymbolAddress((void**)&woq1, g_woq1); cudaGetSymbolAddress((void**)&woq2, g_woq2);
    cudaGetSymbolAddress((void**)&swo, g_swo);
    cudaGetSymbolAddress((void**)&eq1, g_eq1);   cudaGetSymbolAddress((void**)&eq2, g_eq2);
    cudaGetSymbolAddress((void**)&se, g_se);
    cudaGetSymbolAddress((void**)&qh, g_qh);     cudaGetSymbolAddress((void**)&ql, g_ql);
    cudaGetSymbolAddress((void**)&kh, g_kh);     cudaGetSymbolAddress((void**)&kl, g_kl);
    cudaGetSymbolAddress((void**)&vh, g_vh);     cudaGetSymbolAddress((void**)&vl, g_vl);

    cudaFuncSetAttribute(igemm_f32, cudaFuncAttributeMaxDynamicSharedMemorySize, IG_SMEM);
    cudaFuncSetAttribute(igemm_kv,  cudaFuncAttributeMaxDynamicSharedMemorySize, IG_SMEM);
    cudaFuncSetAttribute(attn_mma,  cudaFuncAttributeMaxDynamicSharedMemorySize, ATTN_SMEM);

    // quantize x and weights
    quant_rows<<<M_, 256>>>(x, xq1, xq2, sx, C_);
    colmax<<<C_/256, 256>>>(wq, swq, C_, C_);
    tquant<<<dim3(C_/32, C_/32), dim3(32,8)>>>(wq, swq, wqq1, wqq2, C_, C_);
    colmax<<<KV/256, 256>>>(wk, swk, C_, KV);
    tquant<<<dim3(KV/32, C_/32), dim3(32,8)>>>(wk, swk, wkq1, wkq2, C_, KV);
    colmax<<<KV/256, 256>>>(wv, swv, C_, KV);
    tquant<<<dim3(KV/32, C_/32), dim3(32,8)>>>(wv, swv, wvq1, wvq2, C_, KV);
    colmax<<<C_/256, 256>>>(wo, swo, C_, C_);
    tquant<<<dim3(C_/32, C_/32), dim3(32,8)>>>(wo, swo, woq1, woq2, C_, C_);

    // projections (int8 tensor cores)
    igemm_f32<<<dim3(C_/128, M_/128), 512, IG_SMEM>>>(xq1, xq2, sx, wqq1, wqq2, swq, gq, C_, C_);
    igemm_kv<<<dim3(KV/128, M_/128, 2), 512, IG_SMEM>>>(xq1, xq2, sx,
                                                        wkq1, wkq2, swk,
                                                        wvq1, wvq2, swv,
                                                        gk, vh, vl);

    // rmsnorm + rope -> split bf16
    const float qscale = 0.08838834764831845f;  // 1/sqrt(128)
    rmsrope_kernel<<<M_, 256>>>(gq, qh, ql, C_, qscale);
    rmsrope_kernel<<<M_, 256>>>(gk, kh, kl, KV, 1.0f);

    // flash attention (bf16x3) -> fp32 enc
    attn_mma<<<dim3(T_/BQ, NH, B_), 256, ATTN_SMEM>>>(qh, ql, kh, kl, vh, vl, genc);

    // quantize enc, output projection (int8)
    quant_rows<<<M_, 256>>>(genc, eq1, eq2, se, C_);
    igemm_f32<<<dim3(C_/128, M_/128), 512, IG_SMEM>>>(eq1, eq2, se, woq1, woq2, swo, out, C_, C_);
}

// round 11
// speedup vs baseline: 1.7374x; 1.7277x over previous
#include <cuda_runtime.h>
#include <cuda_bf16.h>
#include <math.h>
#include <stdint.h>

#define B_  2
#define T_  1024
#define C_  2048
#define NH  16
#define KH  4
#define H_  128
#define M_  (B_*T_)
#define KV  (KH*H_)     // 512

// fp32 scratch
__device__ float g_q[M_ * C_];
__device__ float g_k[M_ * KV];
__device__ float g_enc[M_ * C_];
// int8 quantized operands (digit1, digit2) + per-row scales
__device__ int8_t g_xq1[M_*C_],  g_xq2[M_*C_];
__device__ float  g_sx[M_];
__device__ int8_t g_wqq1[C_*C_], g_wqq2[C_*C_];   // [N,K]
__device__ float  g_swq[C_];
__device__ int8_t g_wkq1[KV*C_], g_wkq2[KV*C_];
__device__ float  g_swk[KV];
__device__ int8_t g_wvq1[KV*C_], g_wvq2[KV*C_];
__device__ float  g_swv[KV];
__device__ int8_t g_woq1[C_*C_], g_woq2[C_*C_];
__device__ float  g_swo[C_];
__device__ int8_t g_eq1[M_*C_],  g_eq2[M_*C_];
__device__ float  g_se[M_];
// bf16 split operands for attention
__device__ __nv_bfloat16 g_qh[M_*C_],  g_ql[M_*C_];
__device__ __nv_bfloat16 g_kh[M_*KV],  g_kl[M_*KV];
__device__ __nv_bfloat16 g_vh[M_*KV],  g_vl[M_*KV];

// ---------------- helpers ----------------
__device__ __forceinline__ void ldsm_x4(uint32_t& r0, uint32_t& r1, uint32_t& r2,
                                        uint32_t& r3, uint32_t addr) {
    asm volatile("ldmatrix.sync.aligned.m8n8.x4.shared.b16 {%0,%1,%2,%3}, [%4];"
                 : "=r"(r0), "=r"(r1), "=r"(r2), "=r"(r3) : "r"(addr));
}
__device__ __forceinline__ void ldsm_x2(uint32_t& r0, uint32_t& r1, uint32_t addr) {
    asm volatile("ldmatrix.sync.aligned.m8n8.x2.shared.b16 {%0,%1}, [%2];"
                 : "=r"(r0), "=r"(r1) : "r"(addr));
}
__device__ __forceinline__ void ldsm_x2t(uint32_t& r0, uint32_t& r1, uint32_t addr) {
    asm volatile("ldmatrix.sync.aligned.m8n8.x2.trans.shared.b16 {%0,%1}, [%2];"
                 : "=r"(r0), "=r"(r1) : "r"(addr));
}
__device__ __forceinline__ void mma16816(float* c, const uint32_t* a, const uint32_t* b) {
    asm volatile("mma.sync.aligned.m16n8k16.row.col.f32.bf16.bf16.f32 "
                 "{%0,%1,%2,%3}, {%4,%5,%6,%7}, {%8,%9}, {%0,%1,%2,%3};"
                 : "+f"(c[0]), "+f"(c[1]), "+f"(c[2]), "+f"(c[3])
                 : "r"(a[0]), "r"(a[1]), "r"(a[2]), "r"(a[3]), "r"(b[0]), "r"(b[1]));
}
__device__ __forceinline__ void imma16832(int32_t* c, const uint32_t* a, const uint32_t* b) {
    asm volatile("mma.sync.aligned.m16n8k32.row.col.s32.s8.s8.s32 "
                 "{%0,%1,%2,%3}, {%4,%5,%6,%7}, {%8,%9}, {%0,%1,%2,%3};"
                 : "+r"(c[0]), "+r"(c[1]), "+r"(c[2]), "+r"(c[3])
                 : "r"(a[0]), "r"(a[1]), "r"(a[2]), "r"(a[3]), "r"(b[0]), "r"(b[1]));
}
__device__ __forceinline__ uint32_t pack_bf2(__nv_bfloat16 a, __nv_bfloat16 b) {
    __nv_bfloat162 t = __halves2bfloat162(a, b);
    return *reinterpret_cast<uint32_t*>(&t);
}
__device__ __forceinline__ uint32_t pack_hi2(float x, float y) {
    return pack_bf2(__float2bfloat16(x), __float2bfloat16(y));
}
__device__ __forceinline__ uint32_t pack_lo2(float x, float y) {
    __nv_bfloat16 hx = __float2bfloat16(x), hy = __float2bfloat16(y);
    return pack_bf2(__float2bfloat16(x - __bfloat162float(hx)),
                    __float2bfloat16(y - __bfloat162float(hy)));
}
__device__ __forceinline__ void cp16(uint32_t s, const void* g) {
    asm volatile("cp.async.cg.shared.global [%0], [%1], 16;" :: "r"(s), "l"(g));
}
__device__ __forceinline__ void cp_commit() { asm volatile("cp.async.commit_group;"); }
template<int N> __device__ __forceinline__ void cp_wait() {
    asm volatile("cp.async.wait_group %0;" :: "n"(N));
}
__device__ __forceinline__ uint32_t smem_u32(const void* p) {
    return (uint32_t)__cvta_generic_to_shared(p);
}

// ---------------------------------------------------------------------------
// Row quantization: per row of [rows, D]: s = max|x|/127; a1=rint(x/s),
// a2=rint((x/s-a1)*254). One block per row.
// ---------------------------------------------------------------------------
__global__ void quant_rows(const float* __restrict__ in, int8_t* __restrict__ q1,
                           int8_t* __restrict__ q2, float* __restrict__ sc, int D) {
    __shared__ float sx[2048];
    __shared__ float swr[8];
    const int row = blockIdx.x;
    const int tid = threadIdx.x;
    const int lane = tid & 31, warp = tid >> 5;
    const float* rp = in + (size_t)row * D;

    float m = 0.f;
    for (int d = tid; d < D; d += 256) {
        float v = rp[d];
        sx[d] = v;
        m = fmaxf(m, fabsf(v));
    }
    #pragma unroll
    for (int off = 16; off > 0; off >>= 1)
        m = fmaxf(m, __shfl_xor_sync(0xffffffffu, m, off));
    if (lane == 0) swr[warp] = m;
    __syncthreads();
    float tot = 0.f;
    #pragma unroll
    for (int w = 0; w < 8; w++) tot = fmaxf(tot, swr[w]);
    const float s = fmaxf(tot, 1e-20f) * (1.0f / 127.0f);
    const float inv = 1.0f / s;
    if (tid == 0) sc[row] = s;

    for (int d = tid; d < D; d += 256) {
        float v = sx[d] * inv;
        float a1 = rintf(v);
        float a2 = rintf((v - a1) * 254.0f);
        q1[(size_t)row * D + d] = (int8_t)(int)a1;
        q2[(size_t)row * D + d] = (int8_t)(int)a2;
    }
}

// Column max of W[K,N] -> sB[n] = max/127.
// Block = 256 threads as (32 cols x 8 k-strides); grid = N/32. Coalesced.
__global__ void colmax(const float* __restrict__ W, float* __restrict__ sB, int K, int N) {
    __shared__ float red[8][33];
    const int tx = threadIdx.x & 31;
    const int r = threadIdx.x >> 5;
    const int n = blockIdx.x * 32 + tx;
    float m = 0.f;
    for (int k = r; k < K; k += 8)
        m = fmaxf(m, fabsf(W[(size_t)k * N + n]));
    red[r][tx] = m;
    __syncthreads();
    if (r == 0) {
        #pragma unroll
        for (int i = 1; i < 8; i++) m = fmaxf(m, red[i][tx]);
        sB[n] = fmaxf(m, 1e-20f) * (1.0f / 127.0f);
    }
}

// Transpose + quantize: W[K,N] fp32 -> q1/q2[N,K] s8 using sB[n]
__global__ void tquant(const float* __restrict__ W, const float* __restrict__ sB,
                       int8_t* __restrict__ q1, int8_t* __restrict__ q2, int K, int N) {
    __shared__ float t[32][33];
    const int n0 = blockIdx.x * 32, k0 = blockIdx.y * 32;
    const int tx = threadIdx.x, ty = threadIdx.y;
    #pragma unroll
    for (int i = 0; i < 4; i++)
        t[ty + i * 8][tx] = W[(size_t)(k0 + ty + i * 8) * N + n0 + tx];
    __syncthreads();
    #pragma unroll
    for (int i = 0; i < 4; i++) {
        int n = n0 + ty + i * 8;
        float inv = 1.0f / sB[n];
        float v = t[tx][ty + i * 8] * inv;
        float a1 = rintf(v);
        float a2 = rintf((v - a1) * 254.0f);
        size_t o = (size_t)n * K + k0 + tx;
        q1[o] = (int8_t)(int)a1;
        q2[o] = (int8_t)(int)a2;
    }
}

// ---------------------------------------------------------------------------
// INT8 two-digit GEMM: C[M,N] = (sA*sB) * (S11 + S12/254), tile 128x128,
// BK=64, 512 threads (4x4 warps, warp tile 32x32), 2-stage cp.async.
// ---------------------------------------------------------------------------
#define IBK  64
#define IST  80                 // bytes per smem row slot (conflict-free)
#define ITILE (128*IST)         // 10240 B
#define ISTG (4*ITILE)          // A1,A2,B1,B2 per stage
#define IG_SMEM (2*ISTG)        // 81920 B

template<int OUTMODE>   // 0: fp32, 1: split bf16
__device__ __forceinline__ void igemm_body(
    const int8_t* __restrict__ A1, const int8_t* __restrict__ A2, const float* __restrict__ sA,
    const int8_t* __restrict__ B1, const int8_t* __restrict__ B2, const float* __restrict__ sB,
    float* __restrict__ Cf, __nv_bfloat16* __restrict__ Ch, __nv_bfloat16* __restrict__ Cl,
    int N, int K, int bm0, int bn0)
{
    extern __shared__ int8_t ism[];
    const uint32_t smB = smem_u32(ism);
    const int tid = threadIdx.x;
    const int lane = tid & 31;
    const int warp = tid >> 5;
    const int wm = (warp >> 2) * 32;
    const int wn = (warp & 3) * 32;

    const int pr = tid >> 2, pc = (tid & 3) * 16;

    auto issue = [&](int st, int k0) {
        uint32_t s0 = smB + (uint32_t)st * ISTG + (uint32_t)pr * IST + pc;
        cp16(s0,             A1 + (size_t)(bm0 + pr) * K + k0 + pc);
        cp16(s0 + ITILE,     A2 + (size_t)(bm0 + pr) * K + k0 + pc);
        cp16(s0 + 2 * ITILE, B1 + (size_t)(bn0 + pr) * K + k0 + pc);
        cp16(s0 + 3 * ITILE, B2 + (size_t)(bn0 + pr) * K + k0 + pc);
        cp_commit();
    };

    int32_t hh[2][4][4], xx[2][4][4];
    #pragma unroll
    for (int i = 0; i < 2; i++)
        #pragma unroll
        for (int j = 0; j < 4; j++)
            #pragma unroll
            for (int u = 0; u < 4; u++) { hh[i][j][u] = 0; xx[i][j][u] = 0; }

    const int KT = K / IBK;
    issue(0, 0);
    issue(1, IBK);

    for (int kt = 0; kt < KT; kt++) {
        if (kt == KT - 1) cp_wait<0>(); else cp_wait<1>();
        __syncthreads();
        const uint32_t base = smB + (uint32_t)(kt & 1) * ISTG;

        #pragma unroll
        for (int ks = 0; ks < 2; ks++) {
            uint32_t a1f[2][4], a2f[2][4];
            #pragma unroll
            for (int i = 0; i < 2; i++) {
                uint32_t ad = base + (uint32_t)((wm + i*16 + (lane & 15)) * IST
                              + ((lane >> 4) * 16) + ks * 32);
                ldsm_x4(a1f[i][0], a1f[i][1], a1f[i][2], a1f[i][3], ad);
                ldsm_x4(a2f[i][0], a2f[i][1], a2f[i][2], a2f[i][3], ad + ITILE);
            }
            uint32_t b1f[4][2], b2f[4][2];
            #pragma unroll
            for (int j = 0; j < 4; j++) {
                uint32_t bd = base + 2 * ITILE + (uint32_t)((wn + j*8 + (lane & 7)) * IST
                              + (((lane & 15) >> 3) * 16) + ks * 32);
                ldsm_x2(b1f[j][0], b1f[j][1], bd);
                ldsm_x2(b2f[j][0], b2f[j][1], bd + ITILE);
            }
            #pragma unroll
            for (int i = 0; i < 2; i++)
                #pragma unroll
                for (int j = 0; j < 4; j++) {
                    imma16832(hh[i][j], a1f[i], b1f[j]);
                    imma16832(xx[i][j], a1f[i], b2f[j]);
                    imma16832(xx[i][j], a2f[i], b1f[j]);
                }
        }
        __syncthreads();
        if (kt + 2 < KT) issue(kt & 1, (kt + 2) * IBK);
    }

    const int g = lane >> 2, tg = lane & 3;
    const float r254 = 1.0f / 254.0f;
    #pragma unroll
    for (int i = 0; i < 2; i++) {
        const int ra = bm0 + wm + i * 16 + g;
        const float sa0 = sA[ra], sa1 = sA[ra + 8];
        #pragma unroll
        for (int j = 0; j < 4; j++) {
            const int c0 = bn0 + wn + j * 8 + tg * 2;
            const float sb0 = sB[c0], sb1 = sB[c0 + 1];
            float f00 = sa0 * sb0 * ((float)hh[i][j][0] + (float)xx[i][j][0] * r254);
            float f01 = sa0 * sb1 * ((float)hh[i][j][1] + (float)xx[i][j][1] * r254);
            float f10 = sa1 * sb0 * ((float)hh[i][j][2] + (float)xx[i][j][2] * r254);
            float f11 = sa1 * sb1 * ((float)hh[i][j][3] + (float)xx[i][j][3] * r254);
            if (OUTMODE == 0) {
                *(float2*)&Cf[(size_t)ra * N + c0]       = make_float2(f00, f01);
                *(float2*)&Cf[(size_t)(ra + 8) * N + c0] = make_float2(f10, f11);
            } else {
                *(uint32_t*)&Ch[(size_t)ra * N + c0]       = pack_hi2(f00, f01);
                *(uint32_t*)&Cl[(size_t)ra * N + c0]       = pack_lo2(f00, f01);
                *(uint32_t*)&Ch[(size_t)(ra + 8) * N + c0] = pack_hi2(f10, f11);
                *(uint32_t*)&Cl[(size_t)(ra + 8) * N + c0] = pack_lo2(f10, f11);
            }
        }
    }
}

__global__ __launch_bounds__(512, 1) void igemm_f32(
    const int8_t* A1, const int8_t* A2, const float* sA,
    const int8_t* B1, const int8_t* B2, const float* sB,
    float* C, int N, int K)
{
    igemm_body<0>(A1, A2, sA, B1, B2, sB, C, nullptr, nullptr, N, K,
                  blockIdx.y * 128, blockIdx.x * 128);
}

__global__ __launch_bounds__(512, 1) void igemm_kv(
    const int8_t* A1, const int8_t* A2, const float* sA,
    const int8_t* K1, const int8_t* K2, const float* sK,
    const int8_t* V1, const int8_t* V2, const float* sV,
    float* ck, __nv_bfloat16* cvh, __nv_bfloat16* cvl)
{
    if (blockIdx.z == 0)
        igemm_body<0>(A1, A2, sA, K1, K2, sK, ck, nullptr, nullptr, KV, C_,
                      blockIdx.y * 128, blockIdx.x * 128);
    else
        igemm_body<1>(A1, A2, sA, V1, V2, sV, nullptr, cvh, cvl, KV, C_,
                      blockIdx.y * 128, blockIdx.x * 128);
}

// ---------------------------------------------------------------------------
// Fused RMSNorm + RoPE; reads fp32, writes split bf16.
// ---------------------------------------------------------------------------
__global__ void rmsrope_kernel(const float* __restrict__ buf,
                               __nv_bfloat16* __restrict__ oh, __nv_bfloat16* __restrict__ ol,
                               int D, float scale) {
    __shared__ float s_x[2048];
    __shared__ float s_wred[8];

    const int row = blockIdx.x;
    const int t = row % T_;
    const int tid = threadIdx.x;
    const int lane = tid & 31;
    const int warp = tid >> 5;
    const float* rp = buf + (size_t)row * D;

    float ss = 0.f;
    for (int d = tid; d < D; d += 256) {
        float v = rp[d];
        s_x[d] = v;
        ss = fmaf(v, v, ss);
    }
    #pragma unroll
    for (int off = 16; off > 0; off >>= 1)
        ss += __shfl_xor_sync(0xffffffffu, ss, off);
    if (lane == 0) s_wred[warp] = ss;
    __syncthreads();
    float tot = 0.f;
    #pragma unroll
    for (int w = 0; w < 8; w++) tot += s_wred[w];
    const float inv = rsqrtf(tot / (float)D + 1e-6f) * scale;

    for (int d = tid; d < D; d += 256) {
        int h = d & 127;
        int i = h & 63;
        float fraction = (float)i * (1.0f / 64.0f);
        float inv_freq = powf(10000.0f, -fraction);
        float ang = (float)t * inv_freq;
        float sv = sinf(ang), cv = cosf(ang);
        float xn = s_x[d] * inv;
        float partner = (h < 64) ? s_x[d + 64] : s_x[d - 64];
        partner *= inv;
        float val = (h < 64) ? fmaf(xn, cv, -partner * sv)
                             : fmaf(xn, cv,  partner * sv);
        __nv_bfloat16 hh = __float2bfloat16(val);
        oh[(size_t)row * D + d] = hh;
        ol[(size_t)row * D + d] = __float2bfloat16(val - __bfloat162float(hh));
    }
}

// ---------------------------------------------------------------------------
// Tensor-core flash attention (bf16x3 mma.sync), fp32 enc output.
// ---------------------------------------------------------------------------
#define BQ 128
#define BK 64
#define QS 136

#define AQ_H 0
#define AQ_L (BQ*QS)
#define AKV_BASE (2*BQ*QS)
#define AKV_STG (4*BK*QS)
#define AK_H(st) (AKV_BASE + (st)*AKV_STG)
#define AK_L(st) (AK_H(st) + BK*QS)
#define AV_H(st) (AK_H(st) + 2*BK*QS)
#define AV_L(st) (AK_H(st) + 3*BK*QS)
#define ATTN_SMEM ((AKV_BASE + 2*AKV_STG) * 2)

__global__ __launch_bounds__(256, 1) void attn_mma(
    const __nv_bfloat16* __restrict__ qhp, const __nv_bfloat16* __restrict__ qlp,
    const __nv_bfloat16* __restrict__ khp, const __nv_bfloat16* __restrict__ klp,
    const __nv_bfloat16* __restrict__ vhp, const __nv_bfloat16* __restrict__ vlp,
    float* __restrict__ enc)
{
    extern __shared__ __nv_bfloat16 sm[];
    const uint32_t smB = (uint32_t)__cvta_generic_to_shared(sm);
    const int tid = threadIdx.x;
    const int lane = tid & 31;
    const int warp = tid >> 5;
    const int b = blockIdx.z;
    const int n = blockIdx.y;
    const int khead = n >> 2;
    const int t0 = blockIdx.x * BQ;

    auto issueQ = [&]() {
        #pragma unroll
        for (int j = 0; j < 8; j++) {
            int i = tid + j * 256;
            int row = i >> 4, c = (i & 15) * 8;
            size_t goff = ((size_t)(b * T_ + t0 + row) * C_) + n * H_ + c;
            cp16(smB + (uint32_t)(AQ_H + row * QS + c) * 2, qhp + goff);
            cp16(smB + (uint32_t)(AQ_L + row * QS + c) * 2, qlp + goff);
        }
    };
    auto issueKV = [&](int st, int s0) {
        #pragma unroll
        for (int j = 0; j < 4; j++) {
            int i = tid + j * 256;
            int row = i >> 4, c = (i & 15) * 8;
            size_t goff = ((size_t)(b * T_ + s0 + row) * KV) + khead * H_ + c;
            cp16(smB + (uint32_t)(AK_H(st) + row * QS + c) * 2, khp + goff);
            cp16(smB + (uint32_t)(AK_L(st) + row * QS + c) * 2, klp + goff);
            cp16(smB + (uint32_t)(AV_H(st) + row * QS + c) * 2, vhp + goff);
            cp16(smB + (uint32_t)(AV_L(st) + row * QS + c) * 2, vlp + goff);
        }
        cp_commit();
    };

    issueQ();
    issueKV(0, 0);
    issueKV(1, BK);

    const int g = lane >> 2, tg = lane & 3;
    float m0 = -INFINITY, m1 = -INFINITY, l0 = 0.f, l1 = 0.f;
    float o[16][4];
    #pragma unroll
    for (int nn = 0; nn < 16; nn++)
        #pragma unroll
        for (int u = 0; u < 4; u++) o[nn][u] = 0.f;

    const int NT = T_ / BK;
    for (int stile = 0; stile < NT; stile++) {
        if (stile == NT - 1) cp_wait<0>(); else cp_wait<1>();
        __syncthreads();
        const int st = stile & 1;

        float s[8][4];
        #pragma unroll
        for (int j = 0; j < 8; j++)
            #pragma unroll
            for (int u = 0; u < 4; u++) s[j][u] = 0.f;

        #pragma unroll
        for (int ks = 0; ks < 8; ks++) {
            uint32_t qh[4], ql[4];
            uint32_t qrow = (uint32_t)(warp * 16 + (lane & 15));
            uint32_t qcol = (uint32_t)(ks * 16 + ((lane >> 4) << 3));
            ldsm_x4(qh[0], qh[1], qh[2], qh[3], smB + (uint32_t)(AQ_H + qrow * QS + qcol) * 2);
            ldsm_x4(ql[0], ql[1], ql[2], ql[3], smB + (uint32_t)(AQ_L + qrow * QS + qcol) * 2);
            #pragma unroll
            for (int j = 0; j < 8; j++) {
                uint32_t kh2[2], kl2[2];
                uint32_t krow = (uint32_t)(j * 8 + (lane & 7));
                uint32_t kcol = (uint32_t)(ks * 16 + (((lane & 15) >> 3) << 3));
                ldsm_x2(kh2[0], kh2[1], smB + (uint32_t)(AK_H(st) + krow * QS + kcol) * 2);
                ldsm_x2(kl2[0], kl2[1], smB + (uint32_t)(AK_L(st) + krow * QS + kcol) * 2);
                mma16816(s[j], qh, kh2);
                mma16816(s[j], ql, kh2);
                mma16816(s[j], qh, kl2);
            }
        }

        float mx0 = -INFINITY, mx1 = -INFINITY;
        #pragma unroll
        for (int j = 0; j < 8; j++) {
            mx0 = fmaxf(mx0, fmaxf(s[j][0], s[j][1]));
            mx1 = fmaxf(mx1, fmaxf(s[j][2], s[j][3]));
        }
        mx0 = fmaxf(mx0, __shfl_xor_sync(0xffffffffu, mx0, 1));
        mx0 = fmaxf(mx0, __shfl_xor_sync(0xffffffffu, mx0, 2));
        mx1 = fmaxf(mx1, __shfl_xor_sync(0xffffffffu, mx1, 1));
        mx1 = fmaxf(mx1, __shfl_xor_sync(0xffffffffu, mx1, 2));
        float m0n = fmaxf(m0, mx0);
        float m1n = fmaxf(m1, mx1);
        float a0 = __expf(m0 - m0n);
        float a1 = __expf(m1 - m1n);
        float sum0 = 0.f, sum1 = 0.f;
        #pragma unroll
        for (int j = 0; j < 8; j++) {
            s[j][0] = __expf(s[j][0] - m0n);
            s[j][1] = __expf(s[j][1] - m0n);
            s[j][2] = __expf(s[j][2] - m1n);
            s[j][3] = __expf(s[j][3] - m1n);
            sum0 += s[j][0] + s[j][1];
            sum1 += s[j][2] + s[j][3];
        }
        sum0 += __shfl_xor_sync(0xffffffffu, sum0, 1);
        sum0 += __shfl_xor_sync(0xffffffffu, sum0, 2);
        sum1 += __shfl_xor_sync(0xffffffffu, sum1, 1);
        sum1 += __shfl_xor_sync(0xffffffffu, sum1, 2);
        l0 = l0 * a0 + sum0;
        l1 = l1 * a1 + sum1;
        m0 = m0n; m1 = m1n;
        #pragma unroll
        for (int nn = 0; nn < 16; nn++) {
            o[nn][0] *= a0; o[nn][1] *= a0;
            o[nn][2] *= a1; o[nn][3] *= a1;
        }

        #pragma unroll
        for (int kk = 0; kk < 4; kk++) {
            const int j0 = kk * 2;
            uint32_t ah[4], al[4];
            ah[0] = pack_hi2(s[j0][0],   s[j0][1]);
            ah[1] = pack_hi2(s[j0][2],   s[j0][3]);
            ah[2] = pack_hi2(s[j0+1][0], s[j0+1][1]);
            ah[3] = pack_hi2(s[j0+1][2], s[j0+1][3]);
            al[0] = pack_lo2(s[j0][0],   s[j0][1]);
            al[1] = pack_lo2(s[j0][2],   s[j0][3]);
            al[2] = pack_lo2(s[j0+1][0], s[j0+1][1]);
            al[3] = pack_lo2(s[j0+1][2], s[j0+1][3]);
            #pragma unroll
            for (int nn = 0; nn < 16; nn++) {
                uint32_t bh2[2], bl2[2];
                uint32_t vrow = (uint32_t)(kk * 16 + (lane & 15));
                ldsm_x2t(bh2[0], bh2[1], smB + (uint32_t)(AV_H(st) + vrow * QS + nn * 8) * 2);
                ldsm_x2t(bl2[0], bl2[1], smB + (uint32_t)(AV_L(st) + vrow * QS + nn * 8) * 2);
                mma16816(o[nn], ah, bh2);
                mma16816(o[nn], al, bh2);
                mma16816(o[nn], ah, bl2);
            }
        }

        __syncthreads();
        if (stile + 2 < NT) issueKV(st, (stile + 2) * BK);
    }

    float il0 = 1.0f / l0;
    float il1 = 1.0f / l1;
    const int r0 = t0 + warp * 16 + g;
    #pragma unroll
    for (int nn = 0; nn < 16; nn++) {
        int c0 = nn * 8 + tg * 2;
        size_t base0 = ((size_t)(b * T_ + r0) * C_) + n * H_ + c0;
        size_t base1 = ((size_t)(b * T_ + r0 + 8) * C_) + n * H_ + c0;
        *(float2*)&enc[base0] = make_float2(o[nn][0] * il0, o[nn][1] * il0);
        *(float2*)&enc[base1] = make_float2(o[nn][2] * il1, o[nn][3] * il1);
    }
}

// ---------------------------------------------------------------------------
extern "C" void kernel_launch(void* const* d_in, const int* in_sizes, int n_in,
                              void* d_out, int out_size) {
    const float* x  = (const float*)d_in[0];
    const float* wq = (const float*)d_in[1];
    const float* wk = (const float*)d_in[2];
    const float* wv = (const float*)d_in[3];
    const float* wo = (const float*)d_in[4];
    float* out = (float*)d_out;

    float *gq, *gk, *genc, *sx, *swq, *swk, *swv, *swo, *se;
    int8_t *xq1,*xq2,*wqq1,*wqq2,*wkq1,*wkq2,*wvq1,*wvq2,*woq1,*woq2,*eq1,*eq2;
    __nv_bfloat16 *qh,*ql,*kh,*kl,*vh,*vl;
    cudaGetSymbolAddress((void**)&gq, g_q);
    cudaGetSymbolAddress((void**)&gk, g_k);
    cudaGetSymbolAddress((void**)&genc, g_enc);
    cudaGetSymbolAddress((void**)&xq1, g_xq1);   cudaGetSymbolAddress((void**)&xq2, g_xq2);
    cudaGetSymbolAddress((void**)&sx, g_sx);
    cudaGetSymbolAddress((void**)&wqq1, g_wqq1); cudaGetSymbolAddress((void**)&wqq2, g_wqq2);
    cudaGetSymbolAddress((void**)&swq, g_swq);
    cudaGetSymbolAddress((void**)&wkq1, g_wkq1); cudaGetSymbolAddress((void**)&wkq2, g_wkq2);
    cudaGetSymbolAddress((void**)&swk, g_swk);
    cudaGetSymbolAddress((void**)&wvq1, g_wvq1); cudaGetSymbolAddress((void**)&wvq2, g_wvq2);
    cudaGetSymbolAddress((void**)&swv, g_swv);
    cudaGetSymbolAddress((void**)&woq1, g_woq1); cudaGetSymbolAddress((void**)&woq2, g_woq2);
    cudaGetSymbolAddress((void**)&swo, g_swo);
    cudaGetSymbolAddress((void**)&eq1, g_eq1);   cudaGetSymbolAddress((void**)&eq2, g_eq2);
    cudaGetSymbolAddress((void**)&se, g_se);
    cudaGetSymbolAddress((void**)&qh, g_qh);     cudaGetSymbolAddress((void**)&ql, g_ql);
    cudaGetSymbolAddress((void**)&kh, g_kh);     cudaGetSymbolAddress((void**)&kl, g_kl);
    cudaGetSymbolAddress((void**)&vh, g_vh);     cudaGetSymbolAddress((void**)&vl, g_vl);

    cudaFuncSetAttribute(igemm_f32, cudaFuncAttributeMaxDynamicSharedMemorySize, IG_SMEM);
    cudaFuncSetAttribute(igemm_kv,  cudaFuncAttributeMaxDynamicSharedMemorySize, IG_SMEM);
    cudaFuncSetAttribute(attn_mma,  cudaFuncAttributeMaxDynamicSharedMemorySize, ATTN_SMEM);

    // quantize x and weights
    quant_rows<<<M_, 256>>>(x, xq1, xq2, sx, C_);
    colmax<<<C_/32, 256>>>(wq, swq, C_, C_);
    tquant<<<dim3(C_/32, C_/32), dim3(32,8)>>>(wq, swq, wqq1, wqq2, C_, C_);
    colmax<<<KV/32, 256>>>(wk, swk, C_, KV);
    tquant<<<dim3(KV/32, C_/32), dim3(32,8)>>>(wk, swk, wkq1, wkq2, C_, KV);
    colmax<<<KV/32, 256>>>(wv, swv, C_, KV);
    tquant<<<dim3(KV/32, C_/32), dim3(32,8)>>>(wv, swv, wvq1, wvq2, C_, KV);
    colmax<<<C_/32, 256>>>(wo, swo, C_, C_);
    tquant<<<dim3(C_/32, C_/32), dim3(32,8)>>>(wo, swo, woq1, woq2, C_, C_);

    // projections (int8 tensor cores)
    igemm_f32<<<dim3(C_/128, M_/128), 512, IG_SMEM>>>(xq1, xq2, sx, wqq1, wqq2, swq, gq, C_, C_);
    igemm_kv<<<dim3(KV/128, M_/128, 2), 512, IG_SMEM>>>(xq1, xq2, sx,
                                                        wkq1, wkq2, swk,
                                                        wvq1, wvq2, swv,
                                                        gk, vh, vl);

    // rmsnorm + rope -> split bf16
    const float qscale = 0.08838834764831845f;  // 1/sqrt(128)
    rmsrope_kernel<<<M_, 256>>>(gq, qh, ql, C_, qscale);
    rmsrope_kernel<<<M_, 256>>>(gk, kh, kl, KV, 1.0f);

    // flash attention (bf16x3) -> fp32 enc
    attn_mma<<<dim3(T_/BQ, NH, B_), 256, ATTN_SMEM>>>(qh, ql, kh, kl, vh, vl, genc);

    // quantize enc, output projection (int8)
    quant_rows<<<M_, 256>>>(genc, eq1, eq2, se, C_);
    igemm_f32<<<dim3(C_/128, M_/128), 512, IG_SMEM>>>(eq1, eq2, se, woq1, woq2, swo, out, C_, C_);
}

// round 13
// speedup vs baseline: 1.7466x; 1.0053x over previous
#include <cuda_runtime.h>
#include <cuda_bf16.h>
#include <math.h>
#include <stdint.h>

#define B_  2
#define T_  1024
#define C_  2048
#define NH  16
#define KH  4
#define H_  128
#define M_  (B_*T_)
#define KV  (KH*H_)     // 512

// fp32 scratch
__device__ float g_q[M_ * C_];
__device__ float g_k[M_ * KV];
__device__ float g_enc[M_ * C_];
// int8 quantized operands (digit1, digit2) + per-row scales
__device__ int8_t g_xq1[M_*C_],  g_xq2[M_*C_];
__device__ float  g_sx[M_];
__device__ int8_t g_wqq1[C_*C_], g_wqq2[C_*C_];   // [N,K]
__device__ float  g_swq[C_];
__device__ int8_t g_wkq1[KV*C_], g_wkq2[KV*C_];
__device__ float  g_swk[KV];
__device__ int8_t g_wvq1[KV*C_], g_wvq2[KV*C_];
__device__ float  g_swv[KV];
__device__ int8_t g_woq1[C_*C_], g_woq2[C_*C_];
__device__ float  g_swo[C_];
__device__ int8_t g_eq1[M_*C_],  g_eq2[M_*C_];
__device__ float  g_se[M_];
// bf16 split operands for attention
__device__ __nv_bfloat16 g_qh[M_*C_],  g_ql[M_*C_];
__device__ __nv_bfloat16 g_kh[M_*KV],  g_kl[M_*KV];
__device__ __nv_bfloat16 g_vh[M_*KV],  g_vl[M_*KV];

// ---------------- helpers ----------------
__device__ __forceinline__ void ldsm_x4(uint32_t& r0, uint32_t& r1, uint32_t& r2,
                                        uint32_t& r3, uint32_t addr) {
    asm volatile("ldmatrix.sync.aligned.m8n8.x4.shared.b16 {%0,%1,%2,%3}, [%4];"
                 : "=r"(r0), "=r"(r1), "=r"(r2), "=r"(r3) : "r"(addr));
}
__device__ __forceinline__ void ldsm_x2(uint32_t& r0, uint32_t& r1, uint32_t addr) {
    asm volatile("ldmatrix.sync.aligned.m8n8.x2.shared.b16 {%0,%1}, [%2];"
                 : "=r"(r0), "=r"(r1) : "r"(addr));
}
__device__ __forceinline__ void ldsm_x2t(uint32_t& r0, uint32_t& r1, uint32_t addr) {
    asm volatile("ldmatrix.sync.aligned.m8n8.x2.trans.shared.b16 {%0,%1}, [%2];"
                 : "=r"(r0), "=r"(r1) : "r"(addr));
}
__device__ __forceinline__ void mma16816(float* c, const uint32_t* a, const uint32_t* b) {
    asm volatile("mma.sync.aligned.m16n8k16.row.col.f32.bf16.bf16.f32 "
                 "{%0,%1,%2,%3}, {%4,%5,%6,%7}, {%8,%9}, {%0,%1,%2,%3};"
                 : "+f"(c[0]), "+f"(c[1]), "+f"(c[2]), "+f"(c[3])
                 : "r"(a[0]), "r"(a[1]), "r"(a[2]), "r"(a[3]), "r"(b[0]), "r"(b[1]));
}
__device__ __forceinline__ void imma16832(int32_t* c, const uint32_t* a, const uint32_t* b) {
    asm volatile("mma.sync.aligned.m16n8k32.row.col.s32.s8.s8.s32 "
                 "{%0,%1,%2,%3}, {%4,%5,%6,%7}, {%8,%9}, {%0,%1,%2,%3};"
                 : "+r"(c[0]), "+r"(c[1]), "+r"(c[2]), "+r"(c[3])
                 : "r"(a[0]), "r"(a[1]), "r"(a[2]), "r"(a[3]), "r"(b[0]), "r"(b[1]));
}
__device__ __forceinline__ uint32_t pack_bf2(__nv_bfloat16 a, __nv_bfloat16 b) {
    __nv_bfloat162 t = __halves2bfloat162(a, b);
    return *reinterpret_cast<uint32_t*>(&t);
}
__device__ __forceinline__ uint32_t pack_hi2(float x, float y) {
    return pack_bf2(__float2bfloat16(x), __float2bfloat16(y));
}
__device__ __forceinline__ uint32_t pack_lo2(float x, float y) {
    __nv_bfloat16 hx = __float2bfloat16(x), hy = __float2bfloat16(y);
    return pack_bf2(__float2bfloat16(x - __bfloat162float(hx)),
                    __float2bfloat16(y - __bfloat162float(hy)));
}
__device__ __forceinline__ void cp16(uint32_t s, const void* g) {
    asm volatile("cp.async.cg.shared.global [%0], [%1], 16;" :: "r"(s), "l"(g));
}
__device__ __forceinline__ void cp_commit() { asm volatile("cp.async.commit_group;"); }
template<int N> __device__ __forceinline__ void cp_wait() {
    asm volatile("cp.async.wait_group %0;" :: "n"(N));
}
__device__ __forceinline__ uint32_t smem_u32(const void* p) {
    return (uint32_t)__cvta_generic_to_shared(p);
}

// ---------------------------------------------------------------------------
// Row quantization: per row of [rows, D]: s = max|x|/127; a1=rint(x/s),
// a2=rint((x/s-a1)*254). One block per row.
// ---------------------------------------------------------------------------
__global__ void quant_rows(const float* __restrict__ in, int8_t* __restrict__ q1,
                           int8_t* __restrict__ q2, float* __restrict__ sc, int D) {
    __shared__ float sx[2048];
    __shared__ float swr[8];
    const int row = blockIdx.x;
    const int tid = threadIdx.x;
    const int lane = tid & 31, warp = tid >> 5;
    const float* rp = in + (size_t)row * D;

    float m = 0.f;
    for (int d = tid; d < D; d += 256) {
        float v = rp[d];
        sx[d] = v;
        m = fmaxf(m, fabsf(v));
    }
    #pragma unroll
    for (int off = 16; off > 0; off >>= 1)
        m = fmaxf(m, __shfl_xor_sync(0xffffffffu, m, off));
    if (lane == 0) swr[warp] = m;
    __syncthreads();
    float tot = 0.f;
    #pragma unroll
    for (int w = 0; w < 8; w++) tot = fmaxf(tot, swr[w]);
    const float s = fmaxf(tot, 1e-20f) * (1.0f / 127.0f);
    const float inv = 1.0f / s;
    if (tid == 0) sc[row] = s;

    for (int d = tid; d < D; d += 256) {
        float v = sx[d] * inv;
        float a1 = rintf(v);
        float a2 = rintf((v - a1) * 254.0f);
        q1[(size_t)row * D + d] = (int8_t)(int)a1;
        q2[(size_t)row * D + d] = (int8_t)(int)a2;
    }
}

// Column max of W[K,N] -> sB[n] = max/127.
// Block = 256 threads as (32 cols x 8 k-strides); grid = N/32. Coalesced.
__global__ void colmax(const float* __restrict__ W, float* __restrict__ sB, int K, int N) {
    __shared__ float red[8][33];
    const int tx = threadIdx.x & 31;
    const int r = threadIdx.x >> 5;
    const int n = blockIdx.x * 32 + tx;
    float m = 0.f;
    for (int k = r; k < K; k += 8)
        m = fmaxf(m, fabsf(W[(size_t)k * N + n]));
    red[r][tx] = m;
    __syncthreads();
    if (r == 0) {
        #pragma unroll
        for (int i = 1; i < 8; i++) m = fmaxf(m, red[i][tx]);
        sB[n] = fmaxf(m, 1e-20f) * (1.0f / 127.0f);
    }
}

// Transpose + quantize: W[K,N] fp32 -> q1/q2[N,K] s8 using sB[n]
__global__ void tquant(const float* __restrict__ W, const float* __restrict__ sB,
                       int8_t* __restrict__ q1, int8_t* __restrict__ q2, int K, int N) {
    __shared__ float t[32][33];
    const int n0 = blockIdx.x * 32, k0 = blockIdx.y * 32;
    const int tx = threadIdx.x, ty = threadIdx.y;
    #pragma unroll
    for (int i = 0; i < 4; i++)
        t[ty + i * 8][tx] = W[(size_t)(k0 + ty + i * 8) * N + n0 + tx];
    __syncthreads();
    #pragma unroll
    for (int i = 0; i < 4; i++) {
        int n = n0 + ty + i * 8;
        float inv = 1.0f / sB[n];
        float v = t[tx][ty + i * 8] * inv;
        float a1 = rintf(v);
        float a2 = rintf((v - a1) * 254.0f);
        size_t o = (size_t)n * K + k0 + tx;
        q1[o] = (int8_t)(int)a1;
        q2[o] = (int8_t)(int)a2;
    }
}

// ---------------------------------------------------------------------------
// INT8 two-digit GEMM: C[M,N] = (sA*sB) * (S11 + S12/254), tile 128x128,
// BK=64, 512 threads (4x4 warps, warp tile 32x32), 2-stage cp.async.
// ---------------------------------------------------------------------------
#define IBK  64
#define IST  80                 // bytes per smem row slot (conflict-free)
#define ITILE (128*IST)         // 10240 B
#define ISTG (4*ITILE)          // A1,A2,B1,B2 per stage
#define IG_SMEM (2*ISTG)        // 81920 B

template<int OUTMODE>   // 0: fp32, 1: split bf16
__device__ __forceinline__ void igemm_body(
    const int8_t* __restrict__ A1, const int8_t* __restrict__ A2, const float* __restrict__ sA,
    const int8_t* __restrict__ B1, const int8_t* __restrict__ B2, const float* __restrict__ sB,
    float* __restrict__ Cf, __nv_bfloat16* __restrict__ Ch, __nv_bfloat16* __restrict__ Cl,
    int N, int K, int bm0, int bn0)
{
    extern __shared__ int8_t ism[];
    const uint32_t smB = smem_u32(ism);
    const int tid = threadIdx.x;
    const int lane = tid & 31;
    const int warp = tid >> 5;
    const int wm = (warp >> 2) * 32;
    const int wn = (warp & 3) * 32;

    const int pr = tid >> 2, pc = (tid & 3) * 16;

    auto issue = [&](int st, int k0) {
        uint32_t s0 = smB + (uint32_t)st * ISTG + (uint32_t)pr * IST + pc;
        cp16(s0,             A1 + (size_t)(bm0 + pr) * K + k0 + pc);
        cp16(s0 + ITILE,     A2 + (size_t)(bm0 + pr) * K + k0 + pc);
        cp16(s0 + 2 * ITILE, B1 + (size_t)(bn0 + pr) * K + k0 + pc);
        cp16(s0 + 3 * ITILE, B2 + (size_t)(bn0 + pr) * K + k0 + pc);
        cp_commit();
    };

    int32_t hh[2][4][4], xx[2][4][4];
    #pragma unroll
    for (int i = 0; i < 2; i++)
        #pragma unroll
        for (int j = 0; j < 4; j++)
            #pragma unroll
            for (int u = 0; u < 4; u++) { hh[i][j][u] = 0; xx[i][j][u] = 0; }

    const int KT = K / IBK;
    issue(0, 0);
    issue(1, IBK);

    for (int kt = 0; kt < KT; kt++) {
        if (kt == KT - 1) cp_wait<0>(); else cp_wait<1>();
        __syncthreads();
        const uint32_t base = smB + (uint32_t)(kt & 1) * ISTG;

        #pragma unroll
        for (int ks = 0; ks < 2; ks++) {
            uint32_t a1f[2][4], a2f[2][4];
            #pragma unroll
            for (int i = 0; i < 2; i++) {
                uint32_t ad = base + (uint32_t)((wm + i*16 + (lane & 15)) * IST
                              + ((lane >> 4) * 16) + ks * 32);
                ldsm_x4(a1f[i][0], a1f[i][1], a1f[i][2], a1f[i][3], ad);
                ldsm_x4(a2f[i][0], a2f[i][1], a2f[i][2], a2f[i][3], ad + ITILE);
            }
            uint32_t b1f[4][2], b2f[4][2];
            #pragma unroll
            for (int j = 0; j < 4; j++) {
                uint32_t bd = base + 2 * ITILE + (uint32_t)((wn + j*8 + (lane & 7)) * IST
                              + (((lane & 15) >> 3) * 16) + ks * 32);
                ldsm_x2(b1f[j][0], b1f[j][1], bd);
                ldsm_x2(b2f[j][0], b2f[j][1], bd + ITILE);
            }
            #pragma unroll
            for (int i = 0; i < 2; i++)
                #pragma unroll
                for (int j = 0; j < 4; j++) {
                    imma16832(hh[i][j], a1f[i], b1f[j]);
                    imma16832(xx[i][j], a1f[i], b2f[j]);
                    imma16832(xx[i][j], a2f[i], b1f[j]);
                }
        }
        __syncthreads();
        if (kt + 2 < KT) issue(kt & 1, (kt + 2) * IBK);
    }

    const int g = lane >> 2, tg = lane & 3;
    const float r254 = 1.0f / 254.0f;
    #pragma unroll
    for (int i = 0; i < 2; i++) {
        const int ra = bm0 + wm + i * 16 + g;
        const float sa0 = sA[ra], sa1 = sA[ra + 8];
        #pragma unroll
        for (int j = 0; j < 4; j++) {
            const int c0 = bn0 + wn + j * 8 + tg * 2;
            const float sb0 = sB[c0], sb1 = sB[c0 + 1];
            float f00 = sa0 * sb0 * ((float)hh[i][j][0] + (float)xx[i][j][0] * r254);
            float f01 = sa0 * sb1 * ((float)hh[i][j][1] + (float)xx[i][j][1] * r254);
            float f10 = sa1 * sb0 * ((float)hh[i][j][2] + (float)xx[i][j][2] * r254);
            float f11 = sa1 * sb1 * ((float)hh[i][j][3] + (float)xx[i][j][3] * r254);
            if (OUTMODE == 0) {
                *(float2*)&Cf[(size_t)ra * N + c0]       = make_float2(f00, f01);
                *(float2*)&Cf[(size_t)(ra + 8) * N + c0] = make_float2(f10, f11);
            } else {
                *(uint32_t*)&Ch[(size_t)ra * N + c0]       = pack_hi2(f00, f01);
                *(uint32_t*)&Cl[(size_t)ra * N + c0]       = pack_lo2(f00, f01);
                *(uint32_t*)&Ch[(size_t)(ra + 8) * N + c0] = pack_hi2(f10, f11);
                *(uint32_t*)&Cl[(size_t)(ra + 8) * N + c0] = pack_lo2(f10, f11);
            }
        }
    }
}

__global__ __launch_bounds__(512, 1) void igemm_f32(
    const int8_t* A1, const int8_t* A2, const float* sA,
    const int8_t* B1, const int8_t* B2, const float* sB,
    float* C, int N, int K)
{
    igemm_body<0>(A1, A2, sA, B1, B2, sB, C, nullptr, nullptr, N, K,
                  blockIdx.y * 128, blockIdx.x * 128);
}

__global__ __launch_bounds__(512, 1) void igemm_kv(
    const int8_t* A1, const int8_t* A2, const float* sA,
    const int8_t* K1, const int8_t* K2, const float* sK,
    const int8_t* V1, const int8_t* V2, const float* sV,
    float* ck, __nv_bfloat16* cvh, __nv_bfloat16* cvl)
{
    if (blockIdx.z == 0)
        igemm_body<0>(A1, A2, sA, K1, K2, sK, ck, nullptr, nullptr, KV, C_,
                      blockIdx.y * 128, blockIdx.x * 128);
    else
        igemm_body<1>(A1, A2, sA, V1, V2, sV, nullptr, cvh, cvl, KV, C_,
                      blockIdx.y * 128, blockIdx.x * 128);
}

// ---------------------------------------------------------------------------
// Fused RMSNorm + RoPE; reads fp32, writes split bf16.
// ---------------------------------------------------------------------------
__global__ void rmsrope_kernel(const float* __restrict__ buf,
                               __nv_bfloat16* __restrict__ oh, __nv_bfloat16* __restrict__ ol,
                               int D, float scale) {
    __shared__ float s_x[2048];
    __shared__ float s_wred[8];

    const int row = blockIdx.x;
    const int t = row % T_;
    const int tid = threadIdx.x;
    const int lane = tid & 31;
    const int warp = tid >> 5;
    const float* rp = buf + (size_t)row * D;

    float ss = 0.f;
    for (int d = tid; d < D; d += 256) {
        float v = rp[d];
        s_x[d] = v;
        ss = fmaf(v, v, ss);
    }
    #pragma unroll
    for (int off = 16; off > 0; off >>= 1)
        ss += __shfl_xor_sync(0xffffffffu, ss, off);
    if (lane == 0) s_wred[warp] = ss;
    __syncthreads();
    float tot = 0.f;
    #pragma unroll
    for (int w = 0; w < 8; w++) tot += s_wred[w];
    const float inv = rsqrtf(tot / (float)D + 1e-6f) * scale;

    for (int d = tid; d < D; d += 256) {
        int h = d & 127;
        int i = h & 63;
        float fraction = (float)i * (1.0f / 64.0f);
        float inv_freq = powf(10000.0f, -fraction);
        float ang = (float)t * inv_freq;
        float sv = sinf(ang), cv = cosf(ang);
        float xn = s_x[d] * inv;
        float partner = (h < 64) ? s_x[d + 64] : s_x[d - 64];
        partner *= inv;
        float val = (h < 64) ? fmaf(xn, cv, -partner * sv)
                             : fmaf(xn, cv,  partner * sv);
        __nv_bfloat16 hh = __float2bfloat16(val);
        oh[(size_t)row * D + d] = hh;
        ol[(size_t)row * D + d] = __float2bfloat16(val - __bfloat162float(hh));
    }
}

// ---------------------------------------------------------------------------
// Tensor-core flash attention (bf16x3 mma.sync), fp32 enc output.
// ---------------------------------------------------------------------------
#define BQ 128
#define BK 64
#define QS 136

#define AQ_H 0
#define AQ_L (BQ*QS)
#define AKV_BASE (2*BQ*QS)
#define AKV_STG (4*BK*QS)
#define AK_H(st) (AKV_BASE + (st)*AKV_STG)
#define AK_L(st) (AK_H(st) + BK*QS)
#define AV_H(st) (AK_H(st) + 2*BK*QS)
#define AV_L(st) (AK_H(st) + 3*BK*QS)
#define ATTN_SMEM ((AKV_BASE + 2*AKV_STG) * 2)

__global__ __launch_bounds__(256, 1) void attn_mma(
    const __nv_bfloat16* __restrict__ qhp, const __nv_bfloat16* __restrict__ qlp,
    const __nv_bfloat16* __restrict__ khp, const __nv_bfloat16* __restrict__ klp,
    const __nv_bfloat16* __restrict__ vhp, const __nv_bfloat16* __restrict__ vlp,
    float* __restrict__ enc)
{
    extern __shared__ __nv_bfloat16 sm[];
    const uint32_t smB = (uint32_t)__cvta_generic_to_shared(sm);
    const int tid = threadIdx.x;
    const int lane = tid & 31;
    const int warp = tid >> 5;
    const int b = blockIdx.z;
    const int n = blockIdx.y;
    const int khead = n >> 2;
    const int t0 = blockIdx.x * BQ;

    auto issueQ = [&]() {
        #pragma unroll
        for (int j = 0; j < 8; j++) {
            int i = tid + j * 256;
            int row = i >> 4, c = (i & 15) * 8;
            size_t goff = ((size_t)(b * T_ + t0 + row) * C_) + n * H_ + c;
            cp16(smB + (uint32_t)(AQ_H + row * QS + c) * 2, qhp + goff);
            cp16(smB + (uint32_t)(AQ_L + row * QS + c) * 2, qlp + goff);
        }
    };
    auto issueKV = [&](int st, int s0) {
        #pragma unroll
        for (int j = 0; j < 4; j++) {
            int i = tid + j * 256;
            int row = i >> 4, c = (i & 15) * 8;
            size_t goff = ((size_t)(b * T_ + s0 + row) * KV) + khead * H_ + c;
            cp16(smB + (uint32_t)(AK_H(st) + row * QS + c) * 2, khp + goff);
            cp16(smB + (uint32_t)(AK_L(st) + row * QS + c) * 2, klp + goff);
            cp16(smB + (uint32_t)(AV_H(st) + row * QS + c) * 2, vhp + goff);
            cp16(smB + (uint32_t)(AV_L(st) + row * QS + c) * 2, vlp + goff);
        }
        cp_commit();
    };

    issueQ();
    issueKV(0, 0);
    issueKV(1, BK);

    const int g = lane >> 2, tg = lane & 3;
    float m0 = -INFINITY, m1 = -INFINITY, l0 = 0.f, l1 = 0.f;
    float o[16][4];
    #pragma unroll
    for (int nn = 0; nn < 16; nn++)
        #pragma unroll
        for (int u = 0; u < 4; u++) o[nn][u] = 0.f;

    const int NT = T_ / BK;
    for (int stile = 0; stile < NT; stile++) {
        if (stile == NT - 1) cp_wait<0>(); else cp_wait<1>();
        __syncthreads();
        const int st = stile & 1;

        float s[8][4];
        #pragma unroll
        for (int j = 0; j < 8; j++)
            #pragma unroll
            for (int u = 0; u < 4; u++) s[j][u] = 0.f;

        #pragma unroll
        for (int ks = 0; ks < 8; ks++) {
            uint32_t qh[4], ql[4];
            uint32_t qrow = (uint32_t)(warp * 16 + (lane & 15));
            uint32_t qcol = (uint32_t)(ks * 16 + ((lane >> 4) << 3));
            ldsm_x4(qh[0], qh[1], qh[2], qh[3], smB + (uint32_t)(AQ_H + qrow * QS + qcol) * 2);
            ldsm_x4(ql[0], ql[1], ql[2], ql[3], smB + (uint32_t)(AQ_L + qrow * QS + qcol) * 2);
            #pragma unroll
            for (int j = 0; j < 8; j++) {
                uint32_t kh2[2], kl2[2];
                uint32_t krow = (uint32_t)(j * 8 + (lane & 7));
                uint32_t kcol = (uint32_t)(ks * 16 + (((lane & 15) >> 3) << 3));
                ldsm_x2(kh2[0], kh2[1], smB + (uint32_t)(AK_H(st) + krow * QS + kcol) * 2);
                ldsm_x2(kl2[0], kl2[1], smB + (uint32_t)(AK_L(st) + krow * QS + kcol) * 2);
                mma16816(s[j], qh, kh2);
                mma16816(s[j], ql, kh2);
                mma16816(s[j], qh, kl2);
            }
        }

        float mx0 = -INFINITY, mx1 = -INFINITY;
        #pragma unroll
        for (int j = 0; j < 8; j++) {
            mx0 = fmaxf(mx0, fmaxf(s[j][0], s[j][1]));
            mx1 = fmaxf(mx1, fmaxf(s[j][2], s[j][3]));
        }
        mx0 = fmaxf(mx0, __shfl_xor_sync(0xffffffffu, mx0, 1));
        mx0 = fmaxf(mx0, __shfl_xor_sync(0xffffffffu, mx0, 2));
        mx1 = fmaxf(mx1, __shfl_xor_sync(0xffffffffu, mx1, 1));
        mx1 = fmaxf(mx1, __shfl_xor_sync(0xffffffffu, mx1, 2));
        float m0n = fmaxf(m0, mx0);
        float m1n = fmaxf(m1, mx1);
        float a0 = __expf(m0 - m0n);
        float a1 = __expf(m1 - m1n);
        float sum0 = 0.f, sum1 = 0.f;
        #pragma unroll
        for (int j = 0; j < 8; j++) {
            s[j][0] = __expf(s[j][0] - m0n);
            s[j][1] = __expf(s[j][1] - m0n);
            s[j][2] = __expf(s[j][2] - m1n);
            s[j][3] = __expf(s[j][3] - m1n);
            sum0 += s[j][0] + s[j][1];
            sum1 += s[j][2] + s[j][3];
        }
        sum0 += __shfl_xor_sync(0xffffffffu, sum0, 1);
        sum0 += __shfl_xor_sync(0xffffffffu, sum0, 2);
        sum1 += __shfl_xor_sync(0xffffffffu, sum1, 1);
        sum1 += __shfl_xor_sync(0xffffffffu, sum1, 2);
        l0 = l0 * a0 + sum0;
        l1 = l1 * a1 + sum1;
        m0 = m0n; m1 = m1n;
        #pragma unroll
        for (int nn = 0; nn < 16; nn++) {
            o[nn][0] *= a0; o[nn][1] *= a0;
            o[nn][2] *= a1; o[nn][3] *= a1;
        }

        #pragma unroll
        for (int kk = 0; kk < 4; kk++) {
            const int j0 = kk * 2;
            uint32_t ah[4], al[4];
            ah[0] = pack_hi2(s[j0][0],   s[j0][1]);
            ah[1] = pack_hi2(s[j0][2],   s[j0][3]);
            ah[2] = pack_hi2(s[j0+1][0], s[j0+1][1]);
            ah[3] = pack_hi2(s[j0+1][2], s[j0+1][3]);
            al[0] = pack_lo2(s[j0][0],   s[j0][1]);
            al[1] = pack_lo2(s[j0][2],   s[j0][3]);
            al[2] = pack_lo2(s[j0+1][0], s[j0+1][1]);
            al[3] = pack_lo2(s[j0+1][2], s[j0+1][3]);
            #pragma unroll
            for (int nn = 0; nn < 16; nn++) {
                uint32_t bh2[2], bl2[2];
                uint32_t vrow = (uint32_t)(kk * 16 + (lane & 15));
                ldsm_x2t(bh2[0], bh2[1], smB + (uint32_t)(AV_H(st) + vrow * QS + nn * 8) * 2);
                ldsm_x2t(bl2[0], bl2[1], smB + (uint32_t)(AV_L(st) + vrow * QS + nn * 8) * 2);
                mma16816(o[nn], ah, bh2);
                mma16816(o[nn], al, bh2);
                mma16816(o[nn], ah, bl2);
            }
        }

        __syncthreads();
        if (stile + 2 < NT) issueKV(st, (stile + 2) * BK);
    }

    float il0 = 1.0f / l0;
    float il1 = 1.0f / l1;
    const int r0 = t0 + warp * 16 + g;
    #pragma unroll
    for (int nn = 0; nn < 16; nn++) {
        int c0 = nn * 8 + tg * 2;
        size_t base0 = ((size_t)(b * T_ + r0) * C_) + n * H_ + c0;
        size_t base1 = ((size_t)(b * T_ + r0 + 8) * C_) + n * H_ + c0;
        *(float2*)&enc[base0] = make_float2(o[nn][0] * il0, o[nn][1] * il0);
        *(float2*)&enc[base1] = make_float2(o[nn][2] * il1, o[nn][3] * il1);
    }
}

// ---------------------------------------------------------------------------
extern "C" void kernel_launch(void* const* d_in, const int* in_sizes, int n_in,
                              void* d_out, int out_size) {
    const float* x  = (const float*)d_in[0];
    const float* wq = (const float*)d_in[1];
    const float* wk = (const float*)d_in[2];
    const float* wv = (const float*)d_in[3];
    const float* wo = (const float*)d_in[4];
    float* out = (float*)d_out;

    float *gq, *gk, *genc, *sx, *swq, *swk, *swv, *swo, *se;
    int8_t *xq1,*xq2,*wqq1,*wqq2,*wkq1,*wkq2,*wvq1,*wvq2,*woq1,*woq2,*eq1,*eq2;
    __nv_bfloat16 *qh,*ql,*kh,*kl,*vh,*vl;
    cudaGetSymbolAddress((void**)&gq, g_q);
    cudaGetSymbolAddress((void**)&gk, g_k);
    cudaGetSymbolAddress((void**)&genc, g_enc);
    cudaGetSymbolAddress((void**)&xq1, g_xq1);   cudaGetSymbolAddress((void**)&xq2, g_xq2);
    cudaGetSymbolAddress((void**)&sx, g_sx);
    cudaGetSymbolAddress((void**)&wqq1, g_wqq1); cudaGetSymbolAddress((void**)&wqq2, g_wqq2);
    cudaGetSymbolAddress((void**)&swq, g_swq);
    cudaGetSymbolAddress((void**)&wkq1, g_wkq1); cudaGetSymbolAddress((void**)&wkq2, g_wkq2);
    cudaGetSymbolAddress((void**)&swk, g_swk);
    cudaGetSymbolAddress((void**)&wvq1, g_wvq1); cudaGetSymbolAddress((void**)&wvq2, g_wvq2);
    cudaGetSymbolAddress((void**)&swv, g_swv);
    cudaGetSymbolAddress((void**)&woq1, g_woq1); cudaGetSymbolAddress((void**)&woq2, g_woq2);
    cudaGetSymbolAddress((void**)&swo, g_swo);
    cudaGetSymbolAddress((void**)&eq1, g_eq1);   cudaGetSymbolAddress((void**)&eq2, g_eq2);
    cudaGetSymbolAddress((void**)&se, g_se);
    cudaGetSymbolAddress((void**)&qh, g_qh);     cudaGetSymbolAddress((void**)&ql, g_ql);
    cudaGetSymbolAddress((void**)&kh, g_kh);     cudaGetSymbolAddress((void**)&kl, g_kl);
    cudaGetSymbolAddress((void**)&vh, g_vh);     cudaGetSymbolAddress((void**)&vl, g_vl);

    cudaFuncSetAttribute(igemm_f32, cudaFuncAttributeMaxDynamicSharedMemorySize, IG_SMEM);
    cudaFuncSetAttribute(igemm_kv,  cudaFuncAttributeMaxDynamicSharedMemorySize, IG_SMEM);
    cudaFuncSetAttribute(attn_mma,  cudaFuncAttributeMaxDynamicSharedMemorySize, ATTN_SMEM);

    // quantize x and weights
    quant_rows<<<M_, 256>>>(x, xq1, xq2, sx, C_);
    colmax<<<C_/32, 256>>>(wq, swq, C_, C_);
    tquant<<<dim3(C_/32, C_/32), dim3(32,8)>>>(wq, swq, wqq1, wqq2, C_, C_);
    colmax<<<KV/32, 256>>>(wk, swk, C_, KV);
    tquant<<<dim3(KV/32, C_/32), dim3(32,8)>>>(wk, swk, wkq1, wkq2, C_, KV);
    colmax<<<KV/32, 256>>>(wv, swv, C_, KV);
    tquant<<<dim3(KV/32, C_/32), dim3(32,8)>>>(wv, swv, wvq1, wvq2, C_, KV);
    colmax<<<C_/32, 256>>>(wo, swo, C_, C_);
    tquant<<<dim3(C_/32, C_/32), dim3(32,8)>>>(wo, swo, woq1, woq2, C_, C_);

    // projections (int8 tensor cores)
    igemm_f32<<<dim3(C_/128, M_/128), 512, IG_SMEM>>>(xq1, xq2, sx, wqq1, wqq2, swq, gq, C_, C_);
    igemm_kv<<<dim3(KV/128, M_/128, 2), 512, IG_SMEM>>>(xq1, xq2, sx,
                                                        wkq1, wkq2, swk,
                                                        wvq1, wvq2, swv,
                                                        gk, vh, vl);

    // rmsnorm + rope -> split bf16
    const float qscale = 0.08838834764831845f;  // 1/sqrt(128)
    rmsrope_kernel<<<M_, 256>>>(gq, qh, ql, C_, qscale);
    rmsrope_kernel<<<M_, 256>>>(gk, kh, kl, KV, 1.0f);

    // flash attention (bf16x3) -> fp32 enc
    attn_mma<<<dim3(T_/BQ, NH, B_), 256, ATTN_SMEM>>>(qh, ql, kh, kl, vh, vl, genc);

    // quantize enc, output projection (int8)
    quant_rows<<<M_, 256>>>(genc, eq1, eq2, se, C_);
    igemm_f32<<<dim3(C_/128, M_/128), 512, IG_SMEM>>>(eq1, eq2, se, woq1, woq2, swo, out, C_, C_);
}